// round 14
// baseline (speedup 1.0000x reference)
#include <cuda_runtime.h>

// LQR via parallel-in-time associative Riccati scan + fused forward affine scan.
// ONE persistent kernel, grid=64 x 256thr (2 time-indices per CTA):
//   leaf -> 7 backward suffix levels -> gains -> 7 forward prefix levels
//   -> per-CTA outputs (z, u, mu).
// Grid barriers: RED-arrival counter + separate release-flag line (no shared
// poll/atomic line). Last CTA out resets all state.
// T=128, n_state=16, n_ctrl=8, n_all=24.

constexpr int TT = 128, NS = 16, NC = 8, NA = 24;
constexpr int NLEV = 7;
constexpr int NCTA1 = 64;
constexpr int NBAR = 16;   // 0 leaf, 1..7 backward, 8 post-gains, 9..15 forward

__device__ __align__(16) float EA_[2][TT][NS * NS];  // backward A, then forward M
__device__ __align__(16) float EC_[2][TT][NS * NS];
__device__ __align__(16) float EJ_[2][TT][NS * NS];
__device__ float Eb_[2][TT][NS];                     // backward b, then forward v
__device__ float Ee_[2][TT][NS];
// 128B-padded barrier state: counter and flag on separate lines per level.
__device__ unsigned bctr[NBAR * 32];
__device__ unsigned bflag[NBAR * 32];
__device__ unsigned bfin;

__device__ __forceinline__ void gbar(int k) {
    __syncthreads();
    if (threadIdx.x == 0) {
        __threadfence();
        if (atomicAdd(&bctr[k * 32], 1u) == (unsigned)(NCTA1 - 1)) {
            __threadfence();
            *((volatile unsigned*)&bflag[k * 32]) = 1u;
        } else {
            volatile unsigned* vf = (volatile unsigned*)&bflag[k * 32];
            while (*vf == 0u) {}
        }
        __threadfence();
    }
    __syncthreads();
}

__global__ void __launch_bounds__(256, 1) lqr_kernel(
    const float* __restrict__ A, const float* __restrict__ B,
    const float* __restrict__ x0, const float* __restrict__ C,
    const float* __restrict__ c, float* __restrict__ out)
{
    const int wid = threadIdx.x >> 5, lane = threadIdx.x & 31;
    const int sub = wid & 1;
    const int ltid = ((wid >> 1) << 5) | lane;  // 0..127 within sub
    const int t = blockIdx.x + 64 * sub;

    __shared__ float sC[2][NA][NA + 1];
    __shared__ float sc[2][NA];
    __shared__ float sA[2][NS][NS + 1];
    __shared__ float sB[2][NS][NC + 1];
    __shared__ float oA[2][2][NS][NS + 1];
    __shared__ float oC[2][NS][NS + 1], oJ[2][NS][NS + 1];
    __shared__ float ob[2][NS], oe[2][NS];
    __shared__ float sAj[2][NS][NS + 1], sJj[2][NS][NS + 1], sCj[2][NS][NS + 1];
    __shared__ float sbj[2][NS], sej[2][NS];
    __shared__ float sS[2][NS][NS + 1], sXAT[2][NS][NS + 1], sXCT[2][NS][NS + 1];
    __shared__ float sG[2][NS][NS + 1], sH[2][NS][NS + 1];
    __shared__ float sv[2][NS], sw[2][NS], sXb[2][NS];
    __shared__ float sM[2][NC][NS + 1], sY[2][NC][NS + 1], sm_[2][NC];
    __shared__ float sGb[2][NS][NC + 1];
    __shared__ float sQuu[2][NC][NC + 1], sQux[2][NC][NS + 1], squ[2][NC];
    __shared__ float sx[2][NS];
    __shared__ float sx0[NS];

    // ---------------- Leaf ----------------
    for (int idx = ltid; idx < NA * NA; idx += 128) sC[sub][idx / NA][idx % NA] = C[t * NA * NA + idx];
    for (int idx = ltid; idx < NA; idx += 128)      sc[sub][idx] = c[t * NA + idx];
    for (int idx = ltid; idx < NS * NS; idx += 128) sA[sub][idx / NS][idx % NS] = A[idx];
    for (int idx = ltid; idx < NS * NC; idx += 128) sB[sub][idx / NC][idx % NC] = B[idx];
    if (threadIdx.x < NS) sx0[threadIdx.x] = x0[threadIdx.x];
    __syncthreads();

    if (ltid < 33) {
        float Lm[NC][NC], invd[NC], y[NC];
#pragma unroll
        for (int j = 0; j < NC; ++j)
#pragma unroll
            for (int i = 0; i < NC; ++i)
                if (i >= j) Lm[i][j] = sC[sub][NS + i][NS + j];
#pragma unroll
        for (int j = 0; j < NC; ++j) {
            float r = rsqrtf(Lm[j][j]);
            invd[j] = r;
#pragma unroll
            for (int i = j + 1; i < NC; ++i) Lm[i][j] *= r;
#pragma unroll
            for (int i = j + 1; i < NC; ++i)
#pragma unroll
                for (int l = j + 1; l <= i; ++l)
                    Lm[i][l] = fmaf(-Lm[i][j], Lm[l][j], Lm[i][l]);
        }
#pragma unroll
        for (int a = 0; a < NC; ++a)
            y[a] = (ltid < 16) ? sC[sub][NS + a][ltid]
                 : (ltid < 32) ? sB[sub][ltid - 16][a]
                               : sc[sub][NS + a];
#pragma unroll
        for (int a = 0; a < NC; ++a) {
            float s = y[a];
#pragma unroll
            for (int k = 0; k < a; ++k) s = fmaf(-Lm[a][k], y[k], s);
            y[a] = s * invd[a];
        }
#pragma unroll
        for (int a = NC - 1; a >= 0; --a) {
            float s = y[a];
#pragma unroll
            for (int k = a + 1; k < NC; ++k) s = fmaf(-Lm[k][a], y[k], s);
            y[a] = s * invd[a];
        }
        if (ltid < 16) {
#pragma unroll
            for (int a = 0; a < NC; ++a) sM[sub][a][ltid] = y[a];
        } else if (ltid < 32) {
#pragma unroll
            for (int a = 0; a < NC; ++a) sY[sub][a][ltid - 16] = y[a];
        } else {
#pragma unroll
            for (int a = 0; a < NC; ++a) sm_[sub][a] = y[a];
        }
    }
    __syncthreads();

    {
        const bool last = (t == TT - 1);
        for (int idx = ltid; idx < NS * NS; idx += 128) {
            int i = idx >> 4, j = idx & 15;
            float vJ = sC[sub][i][j], vA = sA[sub][i][j], vC = 0.f;
#pragma unroll
            for (int a = 0; a < NC; ++a) {
                float cxu = sC[sub][i][NS + a], bb = sB[sub][i][a];
                vJ = fmaf(-cxu, sM[sub][a][j], vJ);
                vA = fmaf(-bb, sM[sub][a][j], vA);
                vC = fmaf(bb, sY[sub][a][j], vC);
            }
            if (last) { vA = 0.f; vC = 0.f; }
            oJ[sub][i][j] = vJ; oA[sub][0][i][j] = vA; oC[sub][i][j] = vC;
            EJ_[0][t][idx] = vJ; EA_[0][t][idx] = vA; EC_[0][t][idx] = vC;
        }
        if (ltid < NS) {
            float e = -sc[sub][ltid], b = 0.f;
#pragma unroll
            for (int a = 0; a < NC; ++a) {
                e = fmaf(sC[sub][ltid][NS + a], sm_[sub][a], e);
                b = fmaf(-sB[sub][ltid][a], sm_[sub][a], b);
            }
            if (last) b = 0.f;
            oe[sub][ltid] = e; ob[sub][ltid] = b;
            Ee_[0][t][ltid] = e; Eb_[0][t][ltid] = b;
        }
    }
    gbar(0);

    // ---------------- 7 backward (suffix) levels ----------------
#pragma unroll 1
    for (int k = 0; k < NLEV; ++k) {
        const int d = 1 << k, src = k & 1, dst = src ^ 1, tj = t + d;
        const bool active = (tj < TT);
        const bool lastlev = (k == NLEV - 1);

        if (active) {
            for (int q = ltid; q < NS * NS / 4; q += 128) {
                int r = q >> 2, c0 = (q & 3) * 4;
                float4 va = __ldcg((const float4*)&EA_[src][tj][q * 4]);
                float4 vj = __ldcg((const float4*)&EJ_[src][tj][q * 4]);
                float4 vc = __ldcg((const float4*)&EC_[src][tj][q * 4]);
                sAj[sub][r][c0] = va.x; sAj[sub][r][c0+1] = va.y; sAj[sub][r][c0+2] = va.z; sAj[sub][r][c0+3] = va.w;
                sJj[sub][r][c0] = vj.x; sJj[sub][r][c0+1] = vj.y; sJj[sub][r][c0+2] = vj.z; sJj[sub][r][c0+3] = vj.w;
                sCj[sub][r][c0] = vc.x; sCj[sub][r][c0+1] = vc.y; sCj[sub][r][c0+2] = vc.z; sCj[sub][r][c0+3] = vc.w;
            }
            if (ltid < NS) {
                sbj[sub][ltid] = __ldcg(&Eb_[src][tj][ltid]);
                sej[sub][ltid] = __ldcg(&Ee_[src][tj][ltid]);
            }
        } else {
            for (int idx = ltid; idx < NS * NS; idx += 128) {
                int r = idx >> 4, cc = idx & 15;
                sAj[sub][r][cc] = (r == cc) ? 1.f : 0.f;
                sJj[sub][r][cc] = 0.f; sCj[sub][r][cc] = 0.f;
            }
            if (ltid < NS) { sbj[sub][ltid] = 0.f; sej[sub][ltid] = 0.f; }
        }
        __syncthreads();

        // S = I + Ci*Jj ; v = bi + Ci*etaj
        for (int idx = ltid; idx < NS * NS; idx += 128) {
            int r = idx >> 4, cc = idx & 15;
            float s = (r == cc) ? 1.f : 0.f;
#pragma unroll
            for (int kk = 0; kk < NS; ++kk) s = fmaf(oC[sub][r][kk], sJj[sub][kk][cc], s);
            sS[sub][r][cc] = s;
        }
        if (ltid < NS) {
            float s = ob[sub][ltid];
#pragma unroll
            for (int kk = 0; kk < NS; ++kk) s = fmaf(oC[sub][ltid][kk], sej[sub][kk], s);
            sv[sub][ltid] = s;
        }
        __syncthreads();

        // GJ solve (one warp per sub): S*[XA | Xb | XC] = [Ai | v | Ci]
        if (ltid < 32) {
            float colA[NS], colB[NS];
#pragma unroll
            for (int r = 0; r < NS; ++r) {
                colA[r] = (ltid < NS) ? sS[sub][r][ltid] : oA[sub][src][r][ltid - 16];
                colB[r] = (ltid == 0) ? sv[sub][r] : ((ltid <= 16) ? oC[sub][r][ltid - 1] : 0.f);
            }
#pragma unroll
            for (int p = 0; p < NS; ++p) {
                float f[NS];
#pragma unroll
                for (int r = 0; r < NS; ++r) f[r] = __shfl_sync(0xffffffffu, colA[r], p);
                float inv = __fdividef(1.f, f[p]);
                float mA = colA[p] * inv, mB = colB[p] * inv;
                colA[p] = mA; colB[p] = mB;
#pragma unroll
                for (int r = 0; r < NS; ++r) {
                    if (r != p) {
                        colA[r] = fmaf(-f[r], mA, colA[r]);
                        colB[r] = fmaf(-f[r], mB, colB[r]);
                    }
                }
            }
            if (ltid >= NS) {
#pragma unroll
                for (int r = 0; r < NS; ++r) sXAT[sub][ltid - NS][r] = colA[r];
            }
            if (ltid == 0) {
#pragma unroll
                for (int r = 0; r < NS; ++r) sXb[sub][r] = colB[r];
            } else if (ltid <= 16) {
#pragma unroll
                for (int r = 0; r < NS; ++r) sXCT[sub][ltid - 1][r] = colB[r];
            }
        }
        __syncthreads();

        // Round 1: Aout = Aj XA ; G = Aj XC ; H = Jj XA ; bout ; w
        for (int idx = ltid; idx < NS * NS; idx += 128) {
            int r = idx >> 4, cc = idx & 15;
            float a = 0.f, g = 0.f, h = 0.f;
#pragma unroll
            for (int kk = 0; kk < NS; ++kk) {
                a = fmaf(sAj[sub][r][kk], sXAT[sub][cc][kk], a);
                g = fmaf(sAj[sub][r][kk], sXCT[sub][cc][kk], g);
                h = fmaf(sJj[sub][r][kk], sXAT[sub][cc][kk], h);
            }
            oA[sub][dst][r][cc] = a;
            if (!lastlev) EA_[dst][t][idx] = a;
            sG[sub][r][cc] = g; sH[sub][r][cc] = h;
        }
        if (ltid < NS) {
            float b = sbj[sub][ltid], w = sej[sub][ltid];
#pragma unroll
            for (int kk = 0; kk < NS; ++kk) {
                b = fmaf(sAj[sub][ltid][kk], sXb[sub][kk], b);
                w = fmaf(-sJj[sub][ltid][kk], sXb[sub][kk], w);
            }
            ob[sub][ltid] = b;
            if (!lastlev) Eb_[dst][t][ltid] = b;
            sw[sub][ltid] = w;
        }
        __syncthreads();

        // Round 2: Cout = G Aj' + Cj ; Jout = Ji + Ai' H ; etaout = etai + Ai' w
        for (int idx = ltid; idx < NS * NS; idx += 128) {
            int r = idx >> 4, cc = idx & 15;
            float cv = sCj[sub][r][cc];
            float jv = oJ[sub][r][cc];
#pragma unroll
            for (int kk = 0; kk < NS; ++kk) {
                cv = fmaf(sG[sub][r][kk], sAj[sub][cc][kk], cv);
                jv = fmaf(oA[sub][src][kk][r], sH[sub][kk][cc], jv);
            }
            oC[sub][r][cc] = cv;
            if (!lastlev) EC_[dst][t][idx] = cv;
            oJ[sub][r][cc] = jv; EJ_[dst][t][idx] = jv;
        }
        if (ltid < NS) {
            float e = oe[sub][ltid];
#pragma unroll
            for (int kk = 0; kk < NS; ++kk) e = fmaf(oA[sub][src][kk][ltid], sw[sub][kk], e);
            oe[sub][ltid] = e; Ee_[dst][t][ltid] = e;
        }
        gbar(k + 1);
    }
    // final backward values in parity 1: EJ_[1], Ee_[1]; oJ/oe hold P_t, eta_t.

    // ---------------- Gains for stage t ----------------
    {
        const bool haveP = (t < TT - 1);
        for (int idx = ltid; idx < NS * NS; idx += 128) {
            int r = idx >> 4, cc = idx & 15;
            sAj[sub][r][cc] = haveP ? __ldcg(&EJ_[1][t + 1][idx]) : 0.f;   // P'
        }
        if (ltid < NS) sv[sub][ltid] = haveP ? -__ldcg(&Ee_[1][t + 1][ltid]) : 0.f; // p'
        __syncthreads();

        for (int idx = ltid; idx < NS * NS; idx += 128) {
            int i = idx >> 4, j = idx & 15;
            float s = 0.f;
#pragma unroll
            for (int kk = 0; kk < NS; ++kk) s = fmaf(sAj[sub][i][kk], sA[sub][kk][j], s);
            sCj[sub][i][j] = s;                       // P'A
        }
        for (int idx = ltid; idx < NS * NC; idx += 128) {
            int i = idx / NC, j = idx % NC;
            float s = 0.f;
#pragma unroll
            for (int kk = 0; kk < NS; ++kk) s = fmaf(sAj[sub][i][kk], sB[sub][kk][j], s);
            sGb[sub][i][j] = s;                       // P'B
        }
        __syncthreads();

        for (int idx = ltid; idx < NC * NC; idx += 128) {
            int a = idx >> 3, b2 = idx & 7;
            float s = sC[sub][NS + a][NS + b2];
#pragma unroll
            for (int i = 0; i < NS; ++i) s = fmaf(sB[sub][i][a], sGb[sub][i][b2], s);
            sQuu[sub][a][b2] = s;
        }
        for (int idx = ltid; idx < NC * NS; idx += 128) {
            int a = idx >> 4, j = idx & 15;
            float s = sC[sub][NS + a][j];
#pragma unroll
            for (int i = 0; i < NS; ++i) s = fmaf(sB[sub][i][a], sCj[sub][i][j], s);
            sQux[sub][a][j] = s;
        }
        if (ltid < NC) {
            float s = sc[sub][NS + ltid];
#pragma unroll
            for (int i = 0; i < NS; ++i) s = fmaf(sB[sub][i][ltid], sv[sub][i], s);
            squ[sub][ltid] = s;
        }
        __syncthreads();

        if (ltid < 17) {
            float Lm[NC][NC], invd[NC], y[NC];
#pragma unroll
            for (int j = 0; j < NC; ++j)
#pragma unroll
                for (int i = 0; i < NC; ++i)
                    if (i >= j) Lm[i][j] = sQuu[sub][i][j];
#pragma unroll
            for (int j = 0; j < NC; ++j) {
                float r = rsqrtf(Lm[j][j]);
                invd[j] = r;
#pragma unroll
                for (int i = j + 1; i < NC; ++i) Lm[i][j] *= r;
#pragma unroll
                for (int i = j + 1; i < NC; ++i)
#pragma unroll
                    for (int l = j + 1; l <= i; ++l)
                        Lm[i][l] = fmaf(-Lm[i][j], Lm[l][j], Lm[i][l]);
            }
#pragma unroll
            for (int a = 0; a < NC; ++a)
                y[a] = (ltid < NS) ? sQux[sub][a][ltid] : squ[sub][a];
#pragma unroll
            for (int a = 0; a < NC; ++a) {
                float s = y[a];
#pragma unroll
                for (int kk = 0; kk < a; ++kk) s = fmaf(-Lm[a][kk], y[kk], s);
                y[a] = s * invd[a];
            }
#pragma unroll
            for (int a = NC - 1; a >= 0; --a) {
                float s = y[a];
#pragma unroll
                for (int kk = a + 1; kk < NC; ++kk) s = fmaf(-Lm[kk][a], y[kk], s);
                y[a] = s * invd[a];
            }
            if (ltid < NS) {
#pragma unroll
                for (int a = 0; a < NC; ++a) sM[sub][a][ltid] = y[a];  // K
            } else {
#pragma unroll
                for (int a = 0; a < NC; ++a) sm_[sub][a] = y[a];       // kk
            }
        }
        __syncthreads();

        // Acl = A - B K -> forward element M (sS, EA_[0]); bias -> sv, Eb_[0]
        for (int idx = ltid; idx < NS * NS; idx += 128) {
            int i = idx >> 4, j = idx & 15;
            float s = sA[sub][i][j];
#pragma unroll
            for (int a = 0; a < NC; ++a) s = fmaf(-sB[sub][i][a], sM[sub][a][j], s);
            sS[sub][i][j] = s;
            EA_[0][t][idx] = s;
        }
        if (ltid < NS) {
            float s = 0.f;
#pragma unroll
            for (int a = 0; a < NC; ++a) s = fmaf(-sB[sub][ltid][a], sm_[sub][a], s);
            sv[sub][ltid] = s;
            Eb_[0][t][ltid] = s;
        }
    }
    gbar(8);

    // ---------------- 7 forward (prefix) levels over (Acl, bias) ----------------
    // combine(left, cur) = (M_cur*M_left, M_cur*v_left + v_cur)
#pragma unroll 1
    for (int k = 0; k < NLEV; ++k) {
        const int d = 1 << k, src = k & 1, dst = src ^ 1, tl = t - d;
        if (tl >= 0) {
            for (int q = ltid; q < NS * NS / 4; q += 128) {
                int r = q >> 2, c0 = (q & 3) * 4;
                float4 v = __ldcg((const float4*)&EA_[src][tl][q * 4]);
                sXAT[sub][r][c0] = v.x; sXAT[sub][r][c0+1] = v.y;
                sXAT[sub][r][c0+2] = v.z; sXAT[sub][r][c0+3] = v.w;
            }
            if (ltid < NS) sw[sub][ltid] = __ldcg(&Eb_[src][tl][ltid]);
        } else {
            for (int idx = ltid; idx < NS * NS; idx += 128) {
                int r = idx >> 4, cc = idx & 15;
                sXAT[sub][r][cc] = (r == cc) ? 1.f : 0.f;
            }
            if (ltid < NS) sw[sub][ltid] = 0.f;
        }
        __syncthreads();

        const int r0 = ltid >> 4, c0 = ltid & 15;
        const int r1 = r0 + 8, c1 = c0;
        float m0 = 0.f, m1 = 0.f, vnew = 0.f;
#pragma unroll
        for (int kk = 0; kk < NS; ++kk) {
            m0 = fmaf(sS[sub][r0][kk], sXAT[sub][kk][c0], m0);
            m1 = fmaf(sS[sub][r1][kk], sXAT[sub][kk][c1], m1);
        }
        if (ltid < NS) {
            vnew = sv[sub][ltid];
#pragma unroll
            for (int kk = 0; kk < NS; ++kk) vnew = fmaf(sS[sub][ltid][kk], sw[sub][kk], vnew);
        }
        __syncthreads();
        sS[sub][r0][c0] = m0;              EA_[dst][t][ltid] = m0;
        sS[sub][r1][c1] = m1;              EA_[dst][t][ltid + 128] = m1;
        if (ltid < NS) { sv[sub][ltid] = vnew; Eb_[dst][t][ltid] = vnew; }
        gbar(9 + k);
    }
    // forward prefix in parity 1: EA_[1][t] = S_t.M, Eb_[1][t] = S_t.v

    // ---------------- Outputs for stage t ----------------
    if (ltid < NS) {
        float xi;
        if (t == 0) {
            xi = sx0[ltid];
        } else {
            xi = __ldcg(&Eb_[1][t - 1][ltid]);
#pragma unroll
            for (int q = 0; q < 4; ++q) {
                float4 v = __ldcg((const float4*)&EA_[1][t - 1][ltid * NS + 4 * q]);
                xi = fmaf(v.x, sx0[4 * q + 0], xi); xi = fmaf(v.y, sx0[4 * q + 1], xi);
                xi = fmaf(v.z, sx0[4 * q + 2], xi); xi = fmaf(v.w, sx0[4 * q + 3], xi);
            }
        }
        sx[sub][ltid] = xi;
        out[t * NA + ltid] = xi;
    }
    __syncthreads();
    if (ltid < NC) {
        float s = sm_[sub][ltid];
#pragma unroll
        for (int kk = 0; kk < NS; ++kk) s = fmaf(sM[sub][ltid][kk], sx[sub][kk], s);
        out[t * NA + NS + ltid] = -s;
    } else if (ltid >= 32 && ltid < 48) {
        int i = ltid - 32;
        float s = -oe[sub][i];
#pragma unroll
        for (int kk = 0; kk < NS; ++kk) s = fmaf(oJ[sub][i][kk], sx[sub][kk], s);
        out[TT * NA + t * NS + i] = (t == 0) ? -s : s;
    }

    // ---------------- Last CTA out resets barrier state ----------------
    __threadfence();
    __syncthreads();
    if (threadIdx.x == 0) {
        unsigned v = atomicAdd(&bfin, 1u);
        if (v == (unsigned)NCTA1 - 1) {
            for (int q = 0; q < NBAR; ++q) { bctr[q * 32] = 0u; bflag[q * 32] = 0u; }
            bfin = 0u;
            __threadfence();
        }
    }
}

extern "C" void kernel_launch(void* const* d_in, const int* in_sizes, int n_in,
                              void* d_out, int out_size) {
    const float* A  = (const float*)d_in[0];
    const float* B  = (const float*)d_in[1];
    const float* x0 = (const float*)d_in[2];
    const float* C  = (const float*)d_in[3];
    const float* c  = (const float*)d_in[4];
    float* out = (float*)d_out;

    lqr_kernel<<<NCTA1, 256>>>(A, B, x0, C, c, out);
}

// round 15
// speedup vs baseline: 1.0678x; 1.0678x over previous
#include <cuda_runtime.h>

// LQR via parallel-in-time associative Riccati scan + fused forward affine scan.
// ONE persistent kernel, grid=64 x 256thr (2 time-indices per CTA):
//   leaf -> 7 backward suffix levels -> gains -> 7 forward prefix levels
//   -> per-CTA outputs (z, u, mu).
// Grid barriers: two-level tree (8 groups x 8 CTAs). Level d=64 of both scans
// is intra-CTA (partner = other sub) -> plain __syncthreads, no global trip.
// T=128, n_state=16, n_ctrl=8, n_all=24.

constexpr int TT = 128, NS = 16, NC = 8, NA = 24;
constexpr int NLEV = 7;
constexpr int NCTA1 = 64;
constexpr int NBAR = 16;

__device__ __align__(16) float EA_[2][TT][NS * NS];  // backward A, then forward M
__device__ __align__(16) float EC_[2][TT][NS * NS];
__device__ __align__(16) float EJ_[2][TT][NS * NS];
__device__ float Eb_[2][TT][NS];                     // backward b, then forward v
__device__ float Ee_[2][TT][NS];
// Tree-barrier state, 128B line per counter/flag.
__device__ unsigned gctr[NBAR][8 * 32];
__device__ unsigned groot[NBAR][32];
__device__ unsigned grfl[NBAR][32];
__device__ unsigned ggfl[NBAR][8 * 32];
__device__ unsigned bfin;

__device__ __forceinline__ void gbar(int k) {
    __threadfence();
    __syncthreads();
    if (threadIdx.x == 0) {
        const int g = blockIdx.x >> 3;
        if (atomicAdd(&gctr[k][g * 32], 1u) == 7u) {
            if (atomicAdd(&groot[k][0], 1u) == 7u) {
                *(volatile unsigned*)&grfl[k][0] = 1u;
            } else {
                volatile unsigned* rp = &grfl[k][0];
                while (*rp == 0u) {}
            }
            *(volatile unsigned*)&ggfl[k][g * 32] = 1u;
        } else {
            volatile unsigned* gp = &ggfl[k][g * 32];
            while (*gp == 0u) {}
        }
    }
    __syncthreads();
}

__global__ void __launch_bounds__(256, 1) lqr_kernel(
    const float* __restrict__ A, const float* __restrict__ B,
    const float* __restrict__ x0, const float* __restrict__ C,
    const float* __restrict__ c, float* __restrict__ out)
{
    const int wid = threadIdx.x >> 5, lane = threadIdx.x & 31;
    const int sub = wid & 1;
    const int ltid = ((wid >> 1) << 5) | lane;  // 0..127 within sub
    const int t = blockIdx.x + 64 * sub;

    __shared__ float sC[2][NA][NA + 1];
    __shared__ float sc[2][NA];
    __shared__ float sA[2][NS][NS + 1];
    __shared__ float sB[2][NS][NC + 1];
    __shared__ float oA[2][2][NS][NS + 1];
    __shared__ float oC[2][NS][NS + 1], oJ[2][NS][NS + 1];
    __shared__ float ob[2][NS], oe[2][NS];
    __shared__ float sAj[2][NS][NS + 1], sJj[2][NS][NS + 1], sCj[2][NS][NS + 1];
    __shared__ float sbj[2][NS], sej[2][NS];
    __shared__ float sS[2][NS][NS + 1], sXAT[2][NS][NS + 1], sXCT[2][NS][NS + 1];
    __shared__ float sG[2][NS][NS + 1], sH[2][NS][NS + 1];
    __shared__ float sv[2][NS], sw[2][NS], sXb[2][NS];
    __shared__ float sM[2][NC][NS + 1], sY[2][NC][NS + 1], sm_[2][NC];
    __shared__ float sGb[2][NS][NC + 1];
    __shared__ float sQuu[2][NC][NC + 1], sQux[2][NC][NS + 1], squ[2][NC];
    __shared__ float sx[2][NS];
    __shared__ float sx0[NS];
    __shared__ unsigned slast;

    // ---------------- Leaf ----------------
    for (int idx = ltid; idx < NA * NA; idx += 128) sC[sub][idx / NA][idx % NA] = C[t * NA * NA + idx];
    for (int idx = ltid; idx < NA; idx += 128)      sc[sub][idx] = c[t * NA + idx];
    for (int idx = ltid; idx < NS * NS; idx += 128) sA[sub][idx / NS][idx % NS] = A[idx];
    for (int idx = ltid; idx < NS * NC; idx += 128) sB[sub][idx / NC][idx % NC] = B[idx];
    if (threadIdx.x < NS) sx0[threadIdx.x] = x0[threadIdx.x];
    __syncthreads();

    if (ltid < 33) {
        float Lm[NC][NC], invd[NC], y[NC];
#pragma unroll
        for (int j = 0; j < NC; ++j)
#pragma unroll
            for (int i = 0; i < NC; ++i)
                if (i >= j) Lm[i][j] = sC[sub][NS + i][NS + j];
#pragma unroll
        for (int j = 0; j < NC; ++j) {
            float r = rsqrtf(Lm[j][j]);
            invd[j] = r;
#pragma unroll
            for (int i = j + 1; i < NC; ++i) Lm[i][j] *= r;
#pragma unroll
            for (int i = j + 1; i < NC; ++i)
#pragma unroll
                for (int l = j + 1; l <= i; ++l)
                    Lm[i][l] = fmaf(-Lm[i][j], Lm[l][j], Lm[i][l]);
        }
#pragma unroll
        for (int a = 0; a < NC; ++a)
            y[a] = (ltid < 16) ? sC[sub][NS + a][ltid]
                 : (ltid < 32) ? sB[sub][ltid - 16][a]
                               : sc[sub][NS + a];
#pragma unroll
        for (int a = 0; a < NC; ++a) {
            float s = y[a];
#pragma unroll
            for (int k = 0; k < a; ++k) s = fmaf(-Lm[a][k], y[k], s);
            y[a] = s * invd[a];
        }
#pragma unroll
        for (int a = NC - 1; a >= 0; --a) {
            float s = y[a];
#pragma unroll
            for (int k = a + 1; k < NC; ++k) s = fmaf(-Lm[k][a], y[k], s);
            y[a] = s * invd[a];
        }
        if (ltid < 16) {
#pragma unroll
            for (int a = 0; a < NC; ++a) sM[sub][a][ltid] = y[a];
        } else if (ltid < 32) {
#pragma unroll
            for (int a = 0; a < NC; ++a) sY[sub][a][ltid - 16] = y[a];
        } else {
#pragma unroll
            for (int a = 0; a < NC; ++a) sm_[sub][a] = y[a];
        }
    }
    __syncthreads();

    {
        const bool last = (t == TT - 1);
        for (int idx = ltid; idx < NS * NS; idx += 128) {
            int i = idx >> 4, j = idx & 15;
            float vJ = sC[sub][i][j], vA = sA[sub][i][j], vC = 0.f;
#pragma unroll
            for (int a = 0; a < NC; ++a) {
                float cxu = sC[sub][i][NS + a], bb = sB[sub][i][a];
                vJ = fmaf(-cxu, sM[sub][a][j], vJ);
                vA = fmaf(-bb, sM[sub][a][j], vA);
                vC = fmaf(bb, sY[sub][a][j], vC);
            }
            if (last) { vA = 0.f; vC = 0.f; }
            oJ[sub][i][j] = vJ; oA[sub][0][i][j] = vA; oC[sub][i][j] = vC;
            EJ_[0][t][idx] = vJ; EA_[0][t][idx] = vA; EC_[0][t][idx] = vC;
        }
        if (ltid < NS) {
            float e = -sc[sub][ltid], b = 0.f;
#pragma unroll
            for (int a = 0; a < NC; ++a) {
                e = fmaf(sC[sub][ltid][NS + a], sm_[sub][a], e);
                b = fmaf(-sB[sub][ltid][a], sm_[sub][a], b);
            }
            if (last) b = 0.f;
            oe[sub][ltid] = e; ob[sub][ltid] = b;
            Ee_[0][t][ltid] = e; Eb_[0][t][ltid] = b;
        }
    }
    gbar(0);

    // ---------------- 7 backward (suffix) levels ----------------
#pragma unroll 1
    for (int k = 0; k < NLEV; ++k) {
        const int d = 1 << k, src = k & 1, dst = src ^ 1, tj = t + d;
        const bool active = (tj < TT);

        if (k == NLEV - 1) {
            // d=64: partner is the other sub of this CTA (sub0 <- sub1; sub1 identity)
            if (sub == 0) {
                for (int idx = ltid; idx < NS * NS; idx += 128) {
                    int r = idx >> 4, cc = idx & 15;
                    sAj[0][r][cc] = oA[1][src][r][cc];
                    sJj[0][r][cc] = oJ[1][r][cc];
                    sCj[0][r][cc] = oC[1][r][cc];
                }
                if (ltid < NS) { sbj[0][ltid] = ob[1][ltid]; sej[0][ltid] = oe[1][ltid]; }
            } else {
                for (int idx = ltid; idx < NS * NS; idx += 128) {
                    int r = idx >> 4, cc = idx & 15;
                    sAj[1][r][cc] = (r == cc) ? 1.f : 0.f;
                    sJj[1][r][cc] = 0.f; sCj[1][r][cc] = 0.f;
                }
                if (ltid < NS) { sbj[1][ltid] = 0.f; sej[1][ltid] = 0.f; }
            }
        } else if (active) {
            for (int q = ltid; q < NS * NS / 4; q += 128) {
                int r = q >> 2, c0 = (q & 3) * 4;
                float4 va = __ldcg((const float4*)&EA_[src][tj][q * 4]);
                float4 vj = __ldcg((const float4*)&EJ_[src][tj][q * 4]);
                float4 vc = __ldcg((const float4*)&EC_[src][tj][q * 4]);
                sAj[sub][r][c0] = va.x; sAj[sub][r][c0+1] = va.y; sAj[sub][r][c0+2] = va.z; sAj[sub][r][c0+3] = va.w;
                sJj[sub][r][c0] = vj.x; sJj[sub][r][c0+1] = vj.y; sJj[sub][r][c0+2] = vj.z; sJj[sub][r][c0+3] = vj.w;
                sCj[sub][r][c0] = vc.x; sCj[sub][r][c0+1] = vc.y; sCj[sub][r][c0+2] = vc.z; sCj[sub][r][c0+3] = vc.w;
            }
            if (ltid < NS) {
                sbj[sub][ltid] = __ldcg(&Eb_[src][tj][ltid]);
                sej[sub][ltid] = __ldcg(&Ee_[src][tj][ltid]);
            }
        } else {
            for (int idx = ltid; idx < NS * NS; idx += 128) {
                int r = idx >> 4, cc = idx & 15;
                sAj[sub][r][cc] = (r == cc) ? 1.f : 0.f;
                sJj[sub][r][cc] = 0.f; sCj[sub][r][cc] = 0.f;
            }
            if (ltid < NS) { sbj[sub][ltid] = 0.f; sej[sub][ltid] = 0.f; }
        }
        __syncthreads();

        // S = I + Ci*Jj ; v = bi + Ci*etaj
        for (int idx = ltid; idx < NS * NS; idx += 128) {
            int r = idx >> 4, cc = idx & 15;
            float s = (r == cc) ? 1.f : 0.f;
#pragma unroll
            for (int kk = 0; kk < NS; ++kk) s = fmaf(oC[sub][r][kk], sJj[sub][kk][cc], s);
            sS[sub][r][cc] = s;
        }
        if (ltid < NS) {
            float s = ob[sub][ltid];
#pragma unroll
            for (int kk = 0; kk < NS; ++kk) s = fmaf(oC[sub][ltid][kk], sej[sub][kk], s);
            sv[sub][ltid] = s;
        }
        __syncthreads();

        // GJ solve (one warp per sub): S*[XA | Xb | XC] = [Ai | v | Ci]
        if (ltid < 32) {
            float colA[NS], colB[NS];
#pragma unroll
            for (int r = 0; r < NS; ++r) {
                colA[r] = (ltid < NS) ? sS[sub][r][ltid] : oA[sub][src][r][ltid - 16];
                colB[r] = (ltid == 0) ? sv[sub][r] : ((ltid <= 16) ? oC[sub][r][ltid - 1] : 0.f);
            }
#pragma unroll
            for (int p = 0; p < NS; ++p) {
                float f[NS];
#pragma unroll
                for (int r = 0; r < NS; ++r) f[r] = __shfl_sync(0xffffffffu, colA[r], p);
                float inv = __fdividef(1.f, f[p]);
                float mA = colA[p] * inv, mB = colB[p] * inv;
                colA[p] = mA; colB[p] = mB;
#pragma unroll
                for (int r = 0; r < NS; ++r) {
                    if (r != p) {
                        colA[r] = fmaf(-f[r], mA, colA[r]);
                        colB[r] = fmaf(-f[r], mB, colB[r]);
                    }
                }
            }
            if (ltid >= NS) {
#pragma unroll
                for (int r = 0; r < NS; ++r) sXAT[sub][ltid - NS][r] = colA[r];
            }
            if (ltid == 0) {
#pragma unroll
                for (int r = 0; r < NS; ++r) sXb[sub][r] = colB[r];
            } else if (ltid <= 16) {
#pragma unroll
                for (int r = 0; r < NS; ++r) sXCT[sub][ltid - 1][r] = colB[r];
            }
        }
        __syncthreads();

        // Round 1: Aout = Aj XA ; G = Aj XC ; H = Jj XA ; bout ; w
        for (int idx = ltid; idx < NS * NS; idx += 128) {
            int r = idx >> 4, cc = idx & 15;
            float a = 0.f, g = 0.f, h = 0.f;
#pragma unroll
            for (int kk = 0; kk < NS; ++kk) {
                a = fmaf(sAj[sub][r][kk], sXAT[sub][cc][kk], a);
                g = fmaf(sAj[sub][r][kk], sXCT[sub][cc][kk], g);
                h = fmaf(sJj[sub][r][kk], sXAT[sub][cc][kk], h);
            }
            oA[sub][dst][r][cc] = a; EA_[dst][t][idx] = a;
            sG[sub][r][cc] = g; sH[sub][r][cc] = h;
        }
        if (ltid < NS) {
            float b = sbj[sub][ltid], w = sej[sub][ltid];
#pragma unroll
            for (int kk = 0; kk < NS; ++kk) {
                b = fmaf(sAj[sub][ltid][kk], sXb[sub][kk], b);
                w = fmaf(-sJj[sub][ltid][kk], sXb[sub][kk], w);
            }
            ob[sub][ltid] = b; Eb_[dst][t][ltid] = b;
            sw[sub][ltid] = w;
        }
        __syncthreads();

        // Round 2: Cout = G Aj' + Cj ; Jout = Ji + Ai' H ; etaout = etai + Ai' w
        for (int idx = ltid; idx < NS * NS; idx += 128) {
            int r = idx >> 4, cc = idx & 15;
            float cv = sCj[sub][r][cc];
            float jv = oJ[sub][r][cc];
#pragma unroll
            for (int kk = 0; kk < NS; ++kk) {
                cv = fmaf(sG[sub][r][kk], sAj[sub][cc][kk], cv);
                jv = fmaf(oA[sub][src][kk][r], sH[sub][kk][cc], jv);
            }
            oC[sub][r][cc] = cv; EC_[dst][t][idx] = cv;
            oJ[sub][r][cc] = jv; EJ_[dst][t][idx] = jv;
        }
        if (ltid < NS) {
            float e = oe[sub][ltid];
#pragma unroll
            for (int kk = 0; kk < NS; ++kk) e = fmaf(oA[sub][src][kk][ltid], sw[sub][kk], e);
            oe[sub][ltid] = e; Ee_[dst][t][ltid] = e;
        }
        if (k == NLEV - 2) __syncthreads();   // next level (d=64) is intra-CTA
        else gbar(k + 1);
    }
    // final backward values in parity 1: EJ_[1], Ee_[1]; oJ/oe hold P_t, eta_t.

    // ---------------- Gains for stage t ----------------
    {
        const bool haveP = (t < TT - 1);
        for (int idx = ltid; idx < NS * NS; idx += 128) {
            int r = idx >> 4, cc = idx & 15;
            sAj[sub][r][cc] = haveP ? __ldcg(&EJ_[1][t + 1][idx]) : 0.f;   // P'
        }
        if (ltid < NS) sv[sub][ltid] = haveP ? -__ldcg(&Ee_[1][t + 1][ltid]) : 0.f; // p'
        __syncthreads();

        for (int idx = ltid; idx < NS * NS; idx += 128) {
            int i = idx >> 4, j = idx & 15;
            float s = 0.f;
#pragma unroll
            for (int kk = 0; kk < NS; ++kk) s = fmaf(sAj[sub][i][kk], sA[sub][kk][j], s);
            sCj[sub][i][j] = s;                       // P'A
        }
        for (int idx = ltid; idx < NS * NC; idx += 128) {
            int i = idx / NC, j = idx % NC;
            float s = 0.f;
#pragma unroll
            for (int kk = 0; kk < NS; ++kk) s = fmaf(sAj[sub][i][kk], sB[sub][kk][j], s);
            sGb[sub][i][j] = s;                       // P'B
        }
        __syncthreads();

        for (int idx = ltid; idx < NC * NC; idx += 128) {
            int a = idx >> 3, b2 = idx & 7;
            float s = sC[sub][NS + a][NS + b2];
#pragma unroll
            for (int i = 0; i < NS; ++i) s = fmaf(sB[sub][i][a], sGb[sub][i][b2], s);
            sQuu[sub][a][b2] = s;
        }
        for (int idx = ltid; idx < NC * NS; idx += 128) {
            int a = idx >> 4, j = idx & 15;
            float s = sC[sub][NS + a][j];
#pragma unroll
            for (int i = 0; i < NS; ++i) s = fmaf(sB[sub][i][a], sCj[sub][i][j], s);
            sQux[sub][a][j] = s;
        }
        if (ltid < NC) {
            float s = sc[sub][NS + ltid];
#pragma unroll
            for (int i = 0; i < NS; ++i) s = fmaf(sB[sub][i][ltid], sv[sub][i], s);
            squ[sub][ltid] = s;
        }
        __syncthreads();

        if (ltid < 17) {
            float Lm[NC][NC], invd[NC], y[NC];
#pragma unroll
            for (int j = 0; j < NC; ++j)
#pragma unroll
                for (int i = 0; i < NC; ++i)
                    if (i >= j) Lm[i][j] = sQuu[sub][i][j];
#pragma unroll
            for (int j = 0; j < NC; ++j) {
                float r = rsqrtf(Lm[j][j]);
                invd[j] = r;
#pragma unroll
                for (int i = j + 1; i < NC; ++i) Lm[i][j] *= r;
#pragma unroll
                for (int i = j + 1; i < NC; ++i)
#pragma unroll
                    for (int l = j + 1; l <= i; ++l)
                        Lm[i][l] = fmaf(-Lm[i][j], Lm[l][j], Lm[i][l]);
            }
#pragma unroll
            for (int a = 0; a < NC; ++a)
                y[a] = (ltid < NS) ? sQux[sub][a][ltid] : squ[sub][a];
#pragma unroll
            for (int a = 0; a < NC; ++a) {
                float s = y[a];
#pragma unroll
                for (int kk = 0; kk < a; ++kk) s = fmaf(-Lm[a][kk], y[kk], s);
                y[a] = s * invd[a];
            }
#pragma unroll
            for (int a = NC - 1; a >= 0; --a) {
                float s = y[a];
#pragma unroll
                for (int kk = a + 1; kk < NC; ++kk) s = fmaf(-Lm[kk][a], y[kk], s);
                y[a] = s * invd[a];
            }
            if (ltid < NS) {
#pragma unroll
                for (int a = 0; a < NC; ++a) sM[sub][a][ltid] = y[a];  // K
            } else {
#pragma unroll
                for (int a = 0; a < NC; ++a) sm_[sub][a] = y[a];       // kk
            }
        }
        __syncthreads();

        // Acl = A - B K -> forward element M (sS, EA_[0]); bias -> sv, Eb_[0]
        for (int idx = ltid; idx < NS * NS; idx += 128) {
            int i = idx >> 4, j = idx & 15;
            float s = sA[sub][i][j];
#pragma unroll
            for (int a = 0; a < NC; ++a) s = fmaf(-sB[sub][i][a], sM[sub][a][j], s);
            sS[sub][i][j] = s;
            EA_[0][t][idx] = s;
        }
        if (ltid < NS) {
            float s = 0.f;
#pragma unroll
            for (int a = 0; a < NC; ++a) s = fmaf(-sB[sub][ltid][a], sm_[sub][a], s);
            sv[sub][ltid] = s;
            Eb_[0][t][ltid] = s;
        }
    }
    gbar(8);

    // ---------------- 7 forward (prefix) levels over (Acl, bias) ----------------
    // combine(left, cur) = (M_cur*M_left, M_cur*v_left + v_cur)
#pragma unroll 1
    for (int k = 0; k < NLEV; ++k) {
        const int d = 1 << k, src = k & 1, dst = src ^ 1, tl = t - d;
        if (k == NLEV - 1) {
            // d=64: sub1's left partner is sub0's current element; sub0 identity
            if (sub == 1) {
                for (int idx = ltid; idx < NS * NS; idx += 128) {
                    int r = idx >> 4, cc = idx & 15;
                    sXAT[1][r][cc] = sS[0][r][cc];
                }
                if (ltid < NS) sw[1][ltid] = sv[0][ltid];
            } else {
                for (int idx = ltid; idx < NS * NS; idx += 128) {
                    int r = idx >> 4, cc = idx & 15;
                    sXAT[0][r][cc] = (r == cc) ? 1.f : 0.f;
                }
                if (ltid < NS) sw[0][ltid] = 0.f;
            }
        } else if (tl >= 0) {
            for (int q = ltid; q < NS * NS / 4; q += 128) {
                int r = q >> 2, c0 = (q & 3) * 4;
                float4 v = __ldcg((const float4*)&EA_[src][tl][q * 4]);
                sXAT[sub][r][c0] = v.x; sXAT[sub][r][c0+1] = v.y;
                sXAT[sub][r][c0+2] = v.z; sXAT[sub][r][c0+3] = v.w;
            }
            if (ltid < NS) sw[sub][ltid] = __ldcg(&Eb_[src][tl][ltid]);
        } else {
            for (int idx = ltid; idx < NS * NS; idx += 128) {
                int r = idx >> 4, cc = idx & 15;
                sXAT[sub][r][cc] = (r == cc) ? 1.f : 0.f;
            }
            if (ltid < NS) sw[sub][ltid] = 0.f;
        }
        __syncthreads();

        const int r0 = ltid >> 4, c0 = ltid & 15;
        const int r1 = r0 + 8, c1 = c0;
        float m0 = 0.f, m1 = 0.f, vnew = 0.f;
#pragma unroll
        for (int kk = 0; kk < NS; ++kk) {
            m0 = fmaf(sS[sub][r0][kk], sXAT[sub][kk][c0], m0);
            m1 = fmaf(sS[sub][r1][kk], sXAT[sub][kk][c1], m1);
        }
        if (ltid < NS) {
            vnew = sv[sub][ltid];
#pragma unroll
            for (int kk = 0; kk < NS; ++kk) vnew = fmaf(sS[sub][ltid][kk], sw[sub][kk], vnew);
        }
        __syncthreads();
        sS[sub][r0][c0] = m0;              EA_[dst][t][ltid] = m0;
        sS[sub][r1][c1] = m1;              EA_[dst][t][ltid + 128] = m1;
        if (ltid < NS) { sv[sub][ltid] = vnew; Eb_[dst][t][ltid] = vnew; }
        if (k == NLEV - 2) __syncthreads();   // next level (d=64) is intra-CTA
        else gbar(9 + k);
    }
    // forward prefix in parity 1: EA_[1][t] = S_t.M, Eb_[1][t] = S_t.v

    // ---------------- Outputs for stage t ----------------
    if (ltid < NS) {
        float xi;
        if (t == 0) {
            xi = sx0[ltid];
        } else {
            xi = __ldcg(&Eb_[1][t - 1][ltid]);
#pragma unroll
            for (int q = 0; q < 4; ++q) {
                float4 v = __ldcg((const float4*)&EA_[1][t - 1][ltid * NS + 4 * q]);
                xi = fmaf(v.x, sx0[4 * q + 0], xi); xi = fmaf(v.y, sx0[4 * q + 1], xi);
                xi = fmaf(v.z, sx0[4 * q + 2], xi); xi = fmaf(v.w, sx0[4 * q + 3], xi);
            }
        }
        sx[sub][ltid] = xi;
        out[t * NA + ltid] = xi;
    }
    __syncthreads();
    if (ltid < NC) {
        float s = sm_[sub][ltid];
#pragma unroll
        for (int kk = 0; kk < NS; ++kk) s = fmaf(sM[sub][ltid][kk], sx[sub][kk], s);
        out[t * NA + NS + ltid] = -s;
    } else if (ltid >= 32 && ltid < 48) {
        int i = ltid - 32;
        float s = -oe[sub][i];
#pragma unroll
        for (int kk = 0; kk < NS; ++kk) s = fmaf(oJ[sub][i][kk], sx[sub][kk], s);
        out[TT * NA + t * NS + i] = (t == 0) ? -s : s;
    }

    // ---------------- Last CTA out resets barrier state ----------------
    __threadfence();
    __syncthreads();
    if (threadIdx.x == 0)
        slast = (atomicAdd(&bfin, 1u) == (unsigned)NCTA1 - 1) ? 1u : 0u;
    __syncthreads();
    if (slast) {
        for (int q = threadIdx.x; q < NBAR * 8; q += 256) {
            gctr[q >> 3][(q & 7) * 32] = 0u;
            ggfl[q >> 3][(q & 7) * 32] = 0u;
        }
        if (threadIdx.x < NBAR) { groot[threadIdx.x][0] = 0u; grfl[threadIdx.x][0] = 0u; }
        if (threadIdx.x == 0) { bfin = 0u; }
        __threadfence();
    }
}

extern "C" void kernel_launch(void* const* d_in, const int* in_sizes, int n_in,
                              void* d_out, int out_size) {
    const float* A  = (const float*)d_in[0];
    const float* B  = (const float*)d_in[1];
    const float* x0 = (const float*)d_in[2];
    const float* C  = (const float*)d_in[3];
    const float* c  = (const float*)d_in[4];
    float* out = (float*)d_out;

    lqr_kernel<<<NCTA1, 256>>>(A, B, x0, C, c, out);
}

// round 16
// speedup vs baseline: 1.3031x; 1.2204x over previous
#include <cuda_runtime.h>

// LQR via parallel-in-time associative Riccati scan + fused forward affine scan.
// ONE persistent kernel, grid=64 x 256thr (2 time-indices per CTA):
//   leaf -> 7 backward suffix levels -> gains -> 7 forward prefix levels
//   -> per-CTA outputs (z, u, mu).
// R13 barrier (atomicAdd + poll counter — empirically fastest) kept verbatim;
// level d=64 of both scans is intra-CTA (partner = other sub) -> __syncthreads.
// T=128, n_state=16, n_ctrl=8, n_all=24.

constexpr int TT = 128, NS = 16, NC = 8, NA = 24;
constexpr int NLEV = 7;
constexpr int NCTA1 = 64;
constexpr int NBAR = 16;

__device__ __align__(16) float EA_[2][TT][NS * NS];  // backward A, then forward M
__device__ __align__(16) float EC_[2][TT][NS * NS];
__device__ __align__(16) float EJ_[2][TT][NS * NS];
__device__ float Eb_[2][TT][NS];                     // backward b, then forward v
__device__ float Ee_[2][TT][NS];
__device__ unsigned bctr[NBAR];
__device__ unsigned bfin;

__device__ __forceinline__ void gbar(int k) {
    __threadfence();
    __syncthreads();
    if (threadIdx.x == 0) {
        atomicAdd(&bctr[k], 1u);
        volatile unsigned* vp = &bctr[k];
        while (*vp < (unsigned)NCTA1) {}
    }
    __syncthreads();
}

__global__ void __launch_bounds__(256, 1) lqr_kernel(
    const float* __restrict__ A, const float* __restrict__ B,
    const float* __restrict__ x0, const float* __restrict__ C,
    const float* __restrict__ c, float* __restrict__ out)
{
    const int wid = threadIdx.x >> 5, lane = threadIdx.x & 31;
    const int sub = wid & 1;
    const int ltid = ((wid >> 1) << 5) | lane;  // 0..127 within sub
    const int t = blockIdx.x + 64 * sub;

    __shared__ float sC[2][NA][NA + 1];
    __shared__ float sc[2][NA];
    __shared__ float sA[2][NS][NS + 1];
    __shared__ float sB[2][NS][NC + 1];
    __shared__ float oA[2][2][NS][NS + 1];
    __shared__ float oC[2][NS][NS + 1], oJ[2][NS][NS + 1];
    __shared__ float ob[2][NS], oe[2][NS];
    __shared__ float sAj[2][NS][NS + 1], sJj[2][NS][NS + 1], sCj[2][NS][NS + 1];
    __shared__ float sbj[2][NS], sej[2][NS];
    __shared__ float sS[2][NS][NS + 1], sXAT[2][NS][NS + 1], sXCT[2][NS][NS + 1];
    __shared__ float sG[2][NS][NS + 1], sH[2][NS][NS + 1];
    __shared__ float sv[2][NS], sw[2][NS], sXb[2][NS];
    __shared__ float sM[2][NC][NS + 1], sY[2][NC][NS + 1], sm_[2][NC];
    __shared__ float sGb[2][NS][NC + 1];
    __shared__ float sQuu[2][NC][NC + 1], sQux[2][NC][NS + 1], squ[2][NC];
    __shared__ float sx[2][NS];
    __shared__ float sx0[NS];

    // ---------------- Leaf ----------------
    for (int idx = ltid; idx < NA * NA; idx += 128) sC[sub][idx / NA][idx % NA] = C[t * NA * NA + idx];
    for (int idx = ltid; idx < NA; idx += 128)      sc[sub][idx] = c[t * NA + idx];
    for (int idx = ltid; idx < NS * NS; idx += 128) sA[sub][idx / NS][idx % NS] = A[idx];
    for (int idx = ltid; idx < NS * NC; idx += 128) sB[sub][idx / NC][idx % NC] = B[idx];
    if (threadIdx.x < NS) sx0[threadIdx.x] = x0[threadIdx.x];
    __syncthreads();

    if (ltid < 33) {
        float Lm[NC][NC], invd[NC], y[NC];
#pragma unroll
        for (int j = 0; j < NC; ++j)
#pragma unroll
            for (int i = 0; i < NC; ++i)
                if (i >= j) Lm[i][j] = sC[sub][NS + i][NS + j];
#pragma unroll
        for (int j = 0; j < NC; ++j) {
            float r = rsqrtf(Lm[j][j]);
            invd[j] = r;
#pragma unroll
            for (int i = j + 1; i < NC; ++i) Lm[i][j] *= r;
#pragma unroll
            for (int i = j + 1; i < NC; ++i)
#pragma unroll
                for (int l = j + 1; l <= i; ++l)
                    Lm[i][l] = fmaf(-Lm[i][j], Lm[l][j], Lm[i][l]);
        }
#pragma unroll
        for (int a = 0; a < NC; ++a)
            y[a] = (ltid < 16) ? sC[sub][NS + a][ltid]
                 : (ltid < 32) ? sB[sub][ltid - 16][a]
                               : sc[sub][NS + a];
#pragma unroll
        for (int a = 0; a < NC; ++a) {
            float s = y[a];
#pragma unroll
            for (int k = 0; k < a; ++k) s = fmaf(-Lm[a][k], y[k], s);
            y[a] = s * invd[a];
        }
#pragma unroll
        for (int a = NC - 1; a >= 0; --a) {
            float s = y[a];
#pragma unroll
            for (int k = a + 1; k < NC; ++k) s = fmaf(-Lm[k][a], y[k], s);
            y[a] = s * invd[a];
        }
        if (ltid < 16) {
#pragma unroll
            for (int a = 0; a < NC; ++a) sM[sub][a][ltid] = y[a];
        } else if (ltid < 32) {
#pragma unroll
            for (int a = 0; a < NC; ++a) sY[sub][a][ltid - 16] = y[a];
        } else {
#pragma unroll
            for (int a = 0; a < NC; ++a) sm_[sub][a] = y[a];
        }
    }
    __syncthreads();

    {
        const bool last = (t == TT - 1);
        for (int idx = ltid; idx < NS * NS; idx += 128) {
            int i = idx >> 4, j = idx & 15;
            float vJ = sC[sub][i][j], vA = sA[sub][i][j], vC = 0.f;
#pragma unroll
            for (int a = 0; a < NC; ++a) {
                float cxu = sC[sub][i][NS + a], bb = sB[sub][i][a];
                vJ = fmaf(-cxu, sM[sub][a][j], vJ);
                vA = fmaf(-bb, sM[sub][a][j], vA);
                vC = fmaf(bb, sY[sub][a][j], vC);
            }
            if (last) { vA = 0.f; vC = 0.f; }
            oJ[sub][i][j] = vJ; oA[sub][0][i][j] = vA; oC[sub][i][j] = vC;
            EJ_[0][t][idx] = vJ; EA_[0][t][idx] = vA; EC_[0][t][idx] = vC;
        }
        if (ltid < NS) {
            float e = -sc[sub][ltid], b = 0.f;
#pragma unroll
            for (int a = 0; a < NC; ++a) {
                e = fmaf(sC[sub][ltid][NS + a], sm_[sub][a], e);
                b = fmaf(-sB[sub][ltid][a], sm_[sub][a], b);
            }
            if (last) b = 0.f;
            oe[sub][ltid] = e; ob[sub][ltid] = b;
            Ee_[0][t][ltid] = e; Eb_[0][t][ltid] = b;
        }
    }
    gbar(0);

    // ---------------- 7 backward (suffix) levels ----------------
#pragma unroll 1
    for (int k = 0; k < NLEV; ++k) {
        const int d = 1 << k, src = k & 1, dst = src ^ 1, tj = t + d;
        const bool active = (tj < TT);

        if (k == NLEV - 1) {
            // d=64: partner is the other sub of this CTA (sub0 <- sub1; sub1 identity)
            if (sub == 0) {
                for (int idx = ltid; idx < NS * NS; idx += 128) {
                    int r = idx >> 4, cc = idx & 15;
                    sAj[0][r][cc] = oA[1][src][r][cc];
                    sJj[0][r][cc] = oJ[1][r][cc];
                    sCj[0][r][cc] = oC[1][r][cc];
                }
                if (ltid < NS) { sbj[0][ltid] = ob[1][ltid]; sej[0][ltid] = oe[1][ltid]; }
            } else {
                for (int idx = ltid; idx < NS * NS; idx += 128) {
                    int r = idx >> 4, cc = idx & 15;
                    sAj[1][r][cc] = (r == cc) ? 1.f : 0.f;
                    sJj[1][r][cc] = 0.f; sCj[1][r][cc] = 0.f;
                }
                if (ltid < NS) { sbj[1][ltid] = 0.f; sej[1][ltid] = 0.f; }
            }
        } else if (active) {
            for (int q = ltid; q < NS * NS / 4; q += 128) {
                int r = q >> 2, c0 = (q & 3) * 4;
                float4 va = __ldcg((const float4*)&EA_[src][tj][q * 4]);
                float4 vj = __ldcg((const float4*)&EJ_[src][tj][q * 4]);
                float4 vc = __ldcg((const float4*)&EC_[src][tj][q * 4]);
                sAj[sub][r][c0] = va.x; sAj[sub][r][c0+1] = va.y; sAj[sub][r][c0+2] = va.z; sAj[sub][r][c0+3] = va.w;
                sJj[sub][r][c0] = vj.x; sJj[sub][r][c0+1] = vj.y; sJj[sub][r][c0+2] = vj.z; sJj[sub][r][c0+3] = vj.w;
                sCj[sub][r][c0] = vc.x; sCj[sub][r][c0+1] = vc.y; sCj[sub][r][c0+2] = vc.z; sCj[sub][r][c0+3] = vc.w;
            }
            if (ltid < NS) {
                sbj[sub][ltid] = __ldcg(&Eb_[src][tj][ltid]);
                sej[sub][ltid] = __ldcg(&Ee_[src][tj][ltid]);
            }
        } else {
            for (int idx = ltid; idx < NS * NS; idx += 128) {
                int r = idx >> 4, cc = idx & 15;
                sAj[sub][r][cc] = (r == cc) ? 1.f : 0.f;
                sJj[sub][r][cc] = 0.f; sCj[sub][r][cc] = 0.f;
            }
            if (ltid < NS) { sbj[sub][ltid] = 0.f; sej[sub][ltid] = 0.f; }
        }
        __syncthreads();

        // S = I + Ci*Jj ; v = bi + Ci*etaj
        for (int idx = ltid; idx < NS * NS; idx += 128) {
            int r = idx >> 4, cc = idx & 15;
            float s = (r == cc) ? 1.f : 0.f;
#pragma unroll
            for (int kk = 0; kk < NS; ++kk) s = fmaf(oC[sub][r][kk], sJj[sub][kk][cc], s);
            sS[sub][r][cc] = s;
        }
        if (ltid < NS) {
            float s = ob[sub][ltid];
#pragma unroll
            for (int kk = 0; kk < NS; ++kk) s = fmaf(oC[sub][ltid][kk], sej[sub][kk], s);
            sv[sub][ltid] = s;
        }
        __syncthreads();

        // GJ solve (one warp per sub): S*[XA | Xb | XC] = [Ai | v | Ci]
        if (ltid < 32) {
            float colA[NS], colB[NS];
#pragma unroll
            for (int r = 0; r < NS; ++r) {
                colA[r] = (ltid < NS) ? sS[sub][r][ltid] : oA[sub][src][r][ltid - 16];
                colB[r] = (ltid == 0) ? sv[sub][r] : ((ltid <= 16) ? oC[sub][r][ltid - 1] : 0.f);
            }
#pragma unroll
            for (int p = 0; p < NS; ++p) {
                float f[NS];
#pragma unroll
                for (int r = 0; r < NS; ++r) f[r] = __shfl_sync(0xffffffffu, colA[r], p);
                float inv = __fdividef(1.f, f[p]);
                float mA = colA[p] * inv, mB = colB[p] * inv;
                colA[p] = mA; colB[p] = mB;
#pragma unroll
                for (int r = 0; r < NS; ++r) {
                    if (r != p) {
                        colA[r] = fmaf(-f[r], mA, colA[r]);
                        colB[r] = fmaf(-f[r], mB, colB[r]);
                    }
                }
            }
            if (ltid >= NS) {
#pragma unroll
                for (int r = 0; r < NS; ++r) sXAT[sub][ltid - NS][r] = colA[r];
            }
            if (ltid == 0) {
#pragma unroll
                for (int r = 0; r < NS; ++r) sXb[sub][r] = colB[r];
            } else if (ltid <= 16) {
#pragma unroll
                for (int r = 0; r < NS; ++r) sXCT[sub][ltid - 1][r] = colB[r];
            }
        }
        __syncthreads();

        // Round 1: Aout = Aj XA ; G = Aj XC ; H = Jj XA ; bout ; w
        for (int idx = ltid; idx < NS * NS; idx += 128) {
            int r = idx >> 4, cc = idx & 15;
            float a = 0.f, g = 0.f, h = 0.f;
#pragma unroll
            for (int kk = 0; kk < NS; ++kk) {
                a = fmaf(sAj[sub][r][kk], sXAT[sub][cc][kk], a);
                g = fmaf(sAj[sub][r][kk], sXCT[sub][cc][kk], g);
                h = fmaf(sJj[sub][r][kk], sXAT[sub][cc][kk], h);
            }
            oA[sub][dst][r][cc] = a; EA_[dst][t][idx] = a;
            sG[sub][r][cc] = g; sH[sub][r][cc] = h;
        }
        if (ltid < NS) {
            float b = sbj[sub][ltid], w = sej[sub][ltid];
#pragma unroll
            for (int kk = 0; kk < NS; ++kk) {
                b = fmaf(sAj[sub][ltid][kk], sXb[sub][kk], b);
                w = fmaf(-sJj[sub][ltid][kk], sXb[sub][kk], w);
            }
            ob[sub][ltid] = b; Eb_[dst][t][ltid] = b;
            sw[sub][ltid] = w;
        }
        __syncthreads();

        // Round 2: Cout = G Aj' + Cj ; Jout = Ji + Ai' H ; etaout = etai + Ai' w
        for (int idx = ltid; idx < NS * NS; idx += 128) {
            int r = idx >> 4, cc = idx & 15;
            float cv = sCj[sub][r][cc];
            float jv = oJ[sub][r][cc];
#pragma unroll
            for (int kk = 0; kk < NS; ++kk) {
                cv = fmaf(sG[sub][r][kk], sAj[sub][cc][kk], cv);
                jv = fmaf(oA[sub][src][kk][r], sH[sub][kk][cc], jv);
            }
            oC[sub][r][cc] = cv; EC_[dst][t][idx] = cv;
            oJ[sub][r][cc] = jv; EJ_[dst][t][idx] = jv;
        }
        if (ltid < NS) {
            float e = oe[sub][ltid];
#pragma unroll
            for (int kk = 0; kk < NS; ++kk) e = fmaf(oA[sub][src][kk][ltid], sw[sub][kk], e);
            oe[sub][ltid] = e; Ee_[dst][t][ltid] = e;
        }
        if (k == NLEV - 2) __syncthreads();   // next level (d=64) is intra-CTA
        else gbar(k + 1);
    }
    // final backward values in parity 1: EJ_[1], Ee_[1]; oJ/oe hold P_t, eta_t.

    // ---------------- Gains for stage t ----------------
    {
        const bool haveP = (t < TT - 1);
        for (int idx = ltid; idx < NS * NS; idx += 128) {
            int r = idx >> 4, cc = idx & 15;
            sAj[sub][r][cc] = haveP ? __ldcg(&EJ_[1][t + 1][idx]) : 0.f;   // P'
        }
        if (ltid < NS) sv[sub][ltid] = haveP ? -__ldcg(&Ee_[1][t + 1][ltid]) : 0.f; // p'
        __syncthreads();

        for (int idx = ltid; idx < NS * NS; idx += 128) {
            int i = idx >> 4, j = idx & 15;
            float s = 0.f;
#pragma unroll
            for (int kk = 0; kk < NS; ++kk) s = fmaf(sAj[sub][i][kk], sA[sub][kk][j], s);
            sCj[sub][i][j] = s;                       // P'A
        }
        for (int idx = ltid; idx < NS * NC; idx += 128) {
            int i = idx / NC, j = idx % NC;
            float s = 0.f;
#pragma unroll
            for (int kk = 0; kk < NS; ++kk) s = fmaf(sAj[sub][i][kk], sB[sub][kk][j], s);
            sGb[sub][i][j] = s;                       // P'B
        }
        __syncthreads();

        for (int idx = ltid; idx < NC * NC; idx += 128) {
            int a = idx >> 3, b2 = idx & 7;
            float s = sC[sub][NS + a][NS + b2];
#pragma unroll
            for (int i = 0; i < NS; ++i) s = fmaf(sB[sub][i][a], sGb[sub][i][b2], s);
            sQuu[sub][a][b2] = s;
        }
        for (int idx = ltid; idx < NC * NS; idx += 128) {
            int a = idx >> 4, j = idx & 15;
            float s = sC[sub][NS + a][j];
#pragma unroll
            for (int i = 0; i < NS; ++i) s = fmaf(sB[sub][i][a], sCj[sub][i][j], s);
            sQux[sub][a][j] = s;
        }
        if (ltid < NC) {
            float s = sc[sub][NS + ltid];
#pragma unroll
            for (int i = 0; i < NS; ++i) s = fmaf(sB[sub][i][ltid], sv[sub][i], s);
            squ[sub][ltid] = s;
        }
        __syncthreads();

        if (ltid < 17) {
            float Lm[NC][NC], invd[NC], y[NC];
#pragma unroll
            for (int j = 0; j < NC; ++j)
#pragma unroll
                for (int i = 0; i < NC; ++i)
                    if (i >= j) Lm[i][j] = sQuu[sub][i][j];
#pragma unroll
            for (int j = 0; j < NC; ++j) {
                float r = rsqrtf(Lm[j][j]);
                invd[j] = r;
#pragma unroll
                for (int i = j + 1; i < NC; ++i) Lm[i][j] *= r;
#pragma unroll
                for (int i = j + 1; i < NC; ++i)
#pragma unroll
                    for (int l = j + 1; l <= i; ++l)
                        Lm[i][l] = fmaf(-Lm[i][j], Lm[l][j], Lm[i][l]);
            }
#pragma unroll
            for (int a = 0; a < NC; ++a)
                y[a] = (ltid < NS) ? sQux[sub][a][ltid] : squ[sub][a];
#pragma unroll
            for (int a = 0; a < NC; ++a) {
                float s = y[a];
#pragma unroll
                for (int kk = 0; kk < a; ++kk) s = fmaf(-Lm[a][kk], y[kk], s);
                y[a] = s * invd[a];
            }
#pragma unroll
            for (int a = NC - 1; a >= 0; --a) {
                float s = y[a];
#pragma unroll
                for (int kk = a + 1; kk < NC; ++kk) s = fmaf(-Lm[kk][a], y[kk], s);
                y[a] = s * invd[a];
            }
            if (ltid < NS) {
#pragma unroll
                for (int a = 0; a < NC; ++a) sM[sub][a][ltid] = y[a];  // K
            } else {
#pragma unroll
                for (int a = 0; a < NC; ++a) sm_[sub][a] = y[a];       // kk
            }
        }
        __syncthreads();

        // Acl = A - B K -> forward element M (sS, EA_[0]); bias -> sv, Eb_[0]
        for (int idx = ltid; idx < NS * NS; idx += 128) {
            int i = idx >> 4, j = idx & 15;
            float s = sA[sub][i][j];
#pragma unroll
            for (int a = 0; a < NC; ++a) s = fmaf(-sB[sub][i][a], sM[sub][a][j], s);
            sS[sub][i][j] = s;
            EA_[0][t][idx] = s;
        }
        if (ltid < NS) {
            float s = 0.f;
#pragma unroll
            for (int a = 0; a < NC; ++a) s = fmaf(-sB[sub][ltid][a], sm_[sub][a], s);
            sv[sub][ltid] = s;
            Eb_[0][t][ltid] = s;
        }
    }
    gbar(8);

    // ---------------- 7 forward (prefix) levels over (Acl, bias) ----------------
    // combine(left, cur) = (M_cur*M_left, M_cur*v_left + v_cur)
#pragma unroll 1
    for (int k = 0; k < NLEV; ++k) {
        const int d = 1 << k, src = k & 1, dst = src ^ 1, tl = t - d;
        if (k == NLEV - 1) {
            // d=64: sub1's left partner is sub0's current element; sub0 identity
            if (sub == 1) {
                for (int idx = ltid; idx < NS * NS; idx += 128) {
                    int r = idx >> 4, cc = idx & 15;
                    sXAT[1][r][cc] = sS[0][r][cc];
                }
                if (ltid < NS) sw[1][ltid] = sv[0][ltid];
            } else {
                for (int idx = ltid; idx < NS * NS; idx += 128) {
                    int r = idx >> 4, cc = idx & 15;
                    sXAT[0][r][cc] = (r == cc) ? 1.f : 0.f;
                }
                if (ltid < NS) sw[0][ltid] = 0.f;
            }
        } else if (tl >= 0) {
            for (int q = ltid; q < NS * NS / 4; q += 128) {
                int r = q >> 2, c0 = (q & 3) * 4;
                float4 v = __ldcg((const float4*)&EA_[src][tl][q * 4]);
                sXAT[sub][r][c0] = v.x; sXAT[sub][r][c0+1] = v.y;
                sXAT[sub][r][c0+2] = v.z; sXAT[sub][r][c0+3] = v.w;
            }
            if (ltid < NS) sw[sub][ltid] = __ldcg(&Eb_[src][tl][ltid]);
        } else {
            for (int idx = ltid; idx < NS * NS; idx += 128) {
                int r = idx >> 4, cc = idx & 15;
                sXAT[sub][r][cc] = (r == cc) ? 1.f : 0.f;
            }
            if (ltid < NS) sw[sub][ltid] = 0.f;
        }
        __syncthreads();

        const int r0 = ltid >> 4, c0 = ltid & 15;
        const int r1 = r0 + 8, c1 = c0;
        float m0 = 0.f, m1 = 0.f, vnew = 0.f;
#pragma unroll
        for (int kk = 0; kk < NS; ++kk) {
            m0 = fmaf(sS[sub][r0][kk], sXAT[sub][kk][c0], m0);
            m1 = fmaf(sS[sub][r1][kk], sXAT[sub][kk][c1], m1);
        }
        if (ltid < NS) {
            vnew = sv[sub][ltid];
#pragma unroll
            for (int kk = 0; kk < NS; ++kk) vnew = fmaf(sS[sub][ltid][kk], sw[sub][kk], vnew);
        }
        __syncthreads();
        sS[sub][r0][c0] = m0;              EA_[dst][t][ltid] = m0;
        sS[sub][r1][c1] = m1;              EA_[dst][t][ltid + 128] = m1;
        if (ltid < NS) { sv[sub][ltid] = vnew; Eb_[dst][t][ltid] = vnew; }
        if (k == NLEV - 2) __syncthreads();   // next level (d=64) is intra-CTA
        else gbar(9 + k);
    }
    // forward prefix in parity 1: EA_[1][t] = S_t.M, Eb_[1][t] = S_t.v

    // ---------------- Outputs for stage t ----------------
    if (ltid < NS) {
        float xi;
        if (t == 0) {
            xi = sx0[ltid];
        } else {
            xi = __ldcg(&Eb_[1][t - 1][ltid]);
#pragma unroll
            for (int q = 0; q < 4; ++q) {
                float4 v = __ldcg((const float4*)&EA_[1][t - 1][ltid * NS + 4 * q]);
                xi = fmaf(v.x, sx0[4 * q + 0], xi); xi = fmaf(v.y, sx0[4 * q + 1], xi);
                xi = fmaf(v.z, sx0[4 * q + 2], xi); xi = fmaf(v.w, sx0[4 * q + 3], xi);
            }
        }
        sx[sub][ltid] = xi;
        out[t * NA + ltid] = xi;
    }
    __syncthreads();
    if (ltid < NC) {
        float s = sm_[sub][ltid];
#pragma unroll
        for (int kk = 0; kk < NS; ++kk) s = fmaf(sM[sub][ltid][kk], sx[sub][kk], s);
        out[t * NA + NS + ltid] = -s;
    } else if (ltid >= 32 && ltid < 48) {
        int i = ltid - 32;
        float s = -oe[sub][i];
#pragma unroll
        for (int kk = 0; kk < NS; ++kk) s = fmaf(oJ[sub][i][kk], sx[sub][kk], s);
        out[TT * NA + t * NS + i] = (t == 0) ? -s : s;
    }

    // ---------------- Last CTA out resets barrier state ----------------
    __threadfence();
    __syncthreads();
    if (threadIdx.x == 0) {
        unsigned v = atomicAdd(&bfin, 1u);
        if (v == (unsigned)NCTA1 - 1) {
            for (int q = 0; q < NBAR; ++q) bctr[q] = 0u;
            bfin = 0u;
            __threadfence();
        }
    }
}

extern "C" void kernel_launch(void* const* d_in, const int* in_sizes, int n_in,
                              void* d_out, int out_size) {
    const float* A  = (const float*)d_in[0];
    const float* B  = (const float*)d_in[1];
    const float* x0 = (const float*)d_in[2];
    const float* C  = (const float*)d_in[3];
    const float* c  = (const float*)d_in[4];
    float* out = (float*)d_out;

    lqr_kernel<<<NCTA1, 256>>>(A, B, x0, C, c, out);
}

// round 17
// speedup vs baseline: 1.3052x; 1.0016x over previous
#include <cuda_runtime.h>

// LQR via parallel-in-time associative Riccati scan + fused forward affine scan.
// ONE persistent kernel, grid=64 x 256thr (2 time-indices per CTA).
// NO grid barriers: point-to-point dataflow. Each scan level k writes its
// output to dedicated slot k+1 buffers and publishes a per-CTA flag; readers
// poll only their single producer's flag. Slot chain is a DAG -> deadlock-free.
// Level d=64 of both scans is intra-CTA (partner = other sub).
// T=128, n_state=16, n_ctrl=8, n_all=24.

constexpr int TT = 128, NS = 16, NC = 8, NA = 24;
constexpr int NLEV = 7;
constexpr int NCTA1 = 64;
constexpr int FST = 8;   // flag padding stride (32B)

// Slot buffers: slot 0 = leaf, slot k+1 = output of level k.
__device__ __align__(16) float BA_[NLEV + 1][TT][NS * NS];
__device__ __align__(16) float BC_[NLEV + 1][TT][NS * NS];
__device__ __align__(16) float BJ_[NLEV + 1][TT][NS * NS];
__device__ float Bb_[NLEV + 1][TT][NS];
__device__ float Be_[NLEV + 1][TT][NS];
__device__ __align__(16) float FM_[NLEV + 1][TT][NS * NS];
__device__ float Fv_[NLEV + 1][TT][NS];
__device__ unsigned flB[NLEV + 1][NCTA1 * FST];
__device__ unsigned flF[NLEV + 1][NCTA1 * FST];
__device__ unsigned bfin;

__device__ __forceinline__ void publish(unsigned* f) {
    __threadfence();
    __syncthreads();
    if (threadIdx.x == 0) *(volatile unsigned*)f = 1u;
}
__device__ __forceinline__ void pollflag(unsigned* f) {
    if (threadIdx.x == 0) {
        volatile unsigned* vf = (volatile unsigned*)f;
        while (*vf == 0u) {}
    }
    __syncthreads();
}

__global__ void __launch_bounds__(256, 1) lqr_kernel(
    const float* __restrict__ A, const float* __restrict__ B,
    const float* __restrict__ x0, const float* __restrict__ C,
    const float* __restrict__ c, float* __restrict__ out)
{
    const int wid = threadIdx.x >> 5, lane = threadIdx.x & 31;
    const int sub = wid & 1;
    const int ltid = ((wid >> 1) << 5) | lane;  // 0..127 within sub
    const int bid = blockIdx.x;
    const int t = bid + 64 * sub;

    __shared__ float sC[2][NA][NA + 1];
    __shared__ float sc[2][NA];
    __shared__ float sA[2][NS][NS + 1];
    __shared__ float sB[2][NS][NC + 1];
    __shared__ float oA[2][2][NS][NS + 1];
    __shared__ float oC[2][NS][NS + 1], oJ[2][NS][NS + 1];
    __shared__ float ob[2][NS], oe[2][NS];
    __shared__ float sAj[2][NS][NS + 1], sJj[2][NS][NS + 1], sCj[2][NS][NS + 1];
    __shared__ float sbj[2][NS], sej[2][NS];
    __shared__ float sS[2][NS][NS + 1], sXAT[2][NS][NS + 1], sXCT[2][NS][NS + 1];
    __shared__ float sG[2][NS][NS + 1], sH[2][NS][NS + 1];
    __shared__ float sv[2][NS], sw[2][NS], sXb[2][NS];
    __shared__ float sM[2][NC][NS + 1], sY[2][NC][NS + 1], sm_[2][NC];
    __shared__ float sGb[2][NS][NC + 1];
    __shared__ float sQuu[2][NC][NC + 1], sQux[2][NC][NS + 1], squ[2][NC];
    __shared__ float sx[2][NS];
    __shared__ float sx0[NS];
    __shared__ unsigned slast;

    // ---------------- Leaf ----------------
    for (int idx = ltid; idx < NA * NA; idx += 128) sC[sub][idx / NA][idx % NA] = C[t * NA * NA + idx];
    for (int idx = ltid; idx < NA; idx += 128)      sc[sub][idx] = c[t * NA + idx];
    for (int idx = ltid; idx < NS * NS; idx += 128) sA[sub][idx / NS][idx % NS] = A[idx];
    for (int idx = ltid; idx < NS * NC; idx += 128) sB[sub][idx / NC][idx % NC] = B[idx];
    if (threadIdx.x < NS) sx0[threadIdx.x] = x0[threadIdx.x];
    __syncthreads();

    if (ltid < 33) {
        float Lm[NC][NC], invd[NC], y[NC];
#pragma unroll
        for (int j = 0; j < NC; ++j)
#pragma unroll
            for (int i = 0; i < NC; ++i)
                if (i >= j) Lm[i][j] = sC[sub][NS + i][NS + j];
#pragma unroll
        for (int j = 0; j < NC; ++j) {
            float r = rsqrtf(Lm[j][j]);
            invd[j] = r;
#pragma unroll
            for (int i = j + 1; i < NC; ++i) Lm[i][j] *= r;
#pragma unroll
            for (int i = j + 1; i < NC; ++i)
#pragma unroll
                for (int l = j + 1; l <= i; ++l)
                    Lm[i][l] = fmaf(-Lm[i][j], Lm[l][j], Lm[i][l]);
        }
#pragma unroll
        for (int a = 0; a < NC; ++a)
            y[a] = (ltid < 16) ? sC[sub][NS + a][ltid]
                 : (ltid < 32) ? sB[sub][ltid - 16][a]
                               : sc[sub][NS + a];
#pragma unroll
        for (int a = 0; a < NC; ++a) {
            float s = y[a];
#pragma unroll
            for (int k = 0; k < a; ++k) s = fmaf(-Lm[a][k], y[k], s);
            y[a] = s * invd[a];
        }
#pragma unroll
        for (int a = NC - 1; a >= 0; --a) {
            float s = y[a];
#pragma unroll
            for (int k = a + 1; k < NC; ++k) s = fmaf(-Lm[k][a], y[k], s);
            y[a] = s * invd[a];
        }
        if (ltid < 16) {
#pragma unroll
            for (int a = 0; a < NC; ++a) sM[sub][a][ltid] = y[a];
        } else if (ltid < 32) {
#pragma unroll
            for (int a = 0; a < NC; ++a) sY[sub][a][ltid - 16] = y[a];
        } else {
#pragma unroll
            for (int a = 0; a < NC; ++a) sm_[sub][a] = y[a];
        }
    }
    __syncthreads();

    {
        const bool last = (t == TT - 1);
        for (int idx = ltid; idx < NS * NS; idx += 128) {
            int i = idx >> 4, j = idx & 15;
            float vJ = sC[sub][i][j], vA = sA[sub][i][j], vC = 0.f;
#pragma unroll
            for (int a = 0; a < NC; ++a) {
                float cxu = sC[sub][i][NS + a], bb = sB[sub][i][a];
                vJ = fmaf(-cxu, sM[sub][a][j], vJ);
                vA = fmaf(-bb, sM[sub][a][j], vA);
                vC = fmaf(bb, sY[sub][a][j], vC);
            }
            if (last) { vA = 0.f; vC = 0.f; }
            oJ[sub][i][j] = vJ; oA[sub][0][i][j] = vA; oC[sub][i][j] = vC;
            BJ_[0][t][idx] = vJ; BA_[0][t][idx] = vA; BC_[0][t][idx] = vC;
        }
        if (ltid < NS) {
            float e = -sc[sub][ltid], b = 0.f;
#pragma unroll
            for (int a = 0; a < NC; ++a) {
                e = fmaf(sC[sub][ltid][NS + a], sm_[sub][a], e);
                b = fmaf(-sB[sub][ltid][a], sm_[sub][a], b);
            }
            if (last) b = 0.f;
            oe[sub][ltid] = e; ob[sub][ltid] = b;
            Be_[0][t][ltid] = e; Bb_[0][t][ltid] = b;
        }
    }
    publish(&flB[0][bid * FST]);

    // ---------------- 7 backward (suffix) levels ----------------
#pragma unroll 1
    for (int k = 0; k < NLEV; ++k) {
        const int d = 1 << k, src = k & 1, dst = src ^ 1, tj = t + d;

        if (k == NLEV - 1) {
            // d=64: partner is the other sub (sub0 <- sub1; sub1 identity)
            if (sub == 0) {
                for (int idx = ltid; idx < NS * NS; idx += 128) {
                    int r = idx >> 4, cc = idx & 15;
                    sAj[0][r][cc] = oA[1][src][r][cc];
                    sJj[0][r][cc] = oJ[1][r][cc];
                    sCj[0][r][cc] = oC[1][r][cc];
                }
                if (ltid < NS) { sbj[0][ltid] = ob[1][ltid]; sej[0][ltid] = oe[1][ltid]; }
            } else {
                for (int idx = ltid; idx < NS * NS; idx += 128) {
                    int r = idx >> 4, cc = idx & 15;
                    sAj[1][r][cc] = (r == cc) ? 1.f : 0.f;
                    sJj[1][r][cc] = 0.f; sCj[1][r][cc] = 0.f;
                }
                if (ltid < NS) { sbj[1][ltid] = 0.f; sej[1][ltid] = 0.f; }
            }
        } else {
            pollflag(&flB[k][((bid + d) & 63) * FST]);
            if (tj < TT) {
                for (int q = ltid; q < NS * NS / 4; q += 128) {
                    int r = q >> 2, c0 = (q & 3) * 4;
                    float4 va = __ldcg((const float4*)&BA_[k][tj][q * 4]);
                    float4 vj = __ldcg((const float4*)&BJ_[k][tj][q * 4]);
                    float4 vc = __ldcg((const float4*)&BC_[k][tj][q * 4]);
                    sAj[sub][r][c0] = va.x; sAj[sub][r][c0+1] = va.y; sAj[sub][r][c0+2] = va.z; sAj[sub][r][c0+3] = va.w;
                    sJj[sub][r][c0] = vj.x; sJj[sub][r][c0+1] = vj.y; sJj[sub][r][c0+2] = vj.z; sJj[sub][r][c0+3] = vj.w;
                    sCj[sub][r][c0] = vc.x; sCj[sub][r][c0+1] = vc.y; sCj[sub][r][c0+2] = vc.z; sCj[sub][r][c0+3] = vc.w;
                }
                if (ltid < NS) {
                    sbj[sub][ltid] = __ldcg(&Bb_[k][tj][ltid]);
                    sej[sub][ltid] = __ldcg(&Be_[k][tj][ltid]);
                }
            } else {
                for (int idx = ltid; idx < NS * NS; idx += 128) {
                    int r = idx >> 4, cc = idx & 15;
                    sAj[sub][r][cc] = (r == cc) ? 1.f : 0.f;
                    sJj[sub][r][cc] = 0.f; sCj[sub][r][cc] = 0.f;
                }
                if (ltid < NS) { sbj[sub][ltid] = 0.f; sej[sub][ltid] = 0.f; }
            }
        }
        __syncthreads();

        // S = I + Ci*Jj ; v = bi + Ci*etaj
        for (int idx = ltid; idx < NS * NS; idx += 128) {
            int r = idx >> 4, cc = idx & 15;
            float s = (r == cc) ? 1.f : 0.f;
#pragma unroll
            for (int kk = 0; kk < NS; ++kk) s = fmaf(oC[sub][r][kk], sJj[sub][kk][cc], s);
            sS[sub][r][cc] = s;
        }
        if (ltid < NS) {
            float s = ob[sub][ltid];
#pragma unroll
            for (int kk = 0; kk < NS; ++kk) s = fmaf(oC[sub][ltid][kk], sej[sub][kk], s);
            sv[sub][ltid] = s;
        }
        __syncthreads();

        // GJ solve (one warp per sub): S*[XA | Xb | XC] = [Ai | v | Ci]
        if (ltid < 32) {
            float colA[NS], colB[NS];
#pragma unroll
            for (int r = 0; r < NS; ++r) {
                colA[r] = (ltid < NS) ? sS[sub][r][ltid] : oA[sub][src][r][ltid - 16];
                colB[r] = (ltid == 0) ? sv[sub][r] : ((ltid <= 16) ? oC[sub][r][ltid - 1] : 0.f);
            }
#pragma unroll
            for (int p = 0; p < NS; ++p) {
                float f[NS];
#pragma unroll
                for (int r = 0; r < NS; ++r) f[r] = __shfl_sync(0xffffffffu, colA[r], p);
                float inv = __fdividef(1.f, f[p]);
                float mA = colA[p] * inv, mB = colB[p] * inv;
                colA[p] = mA; colB[p] = mB;
#pragma unroll
                for (int r = 0; r < NS; ++r) {
                    if (r != p) {
                        colA[r] = fmaf(-f[r], mA, colA[r]);
                        colB[r] = fmaf(-f[r], mB, colB[r]);
                    }
                }
            }
            if (ltid >= NS) {
#pragma unroll
                for (int r = 0; r < NS; ++r) sXAT[sub][ltid - NS][r] = colA[r];
            }
            if (ltid == 0) {
#pragma unroll
                for (int r = 0; r < NS; ++r) sXb[sub][r] = colB[r];
            } else if (ltid <= 16) {
#pragma unroll
                for (int r = 0; r < NS; ++r) sXCT[sub][ltid - 1][r] = colB[r];
            }
        }
        __syncthreads();

        const bool storeFull = (k <= 4);   // slots 1..5 read cross-CTA; slot 6 intra-only
        // Round 1: Aout = Aj XA ; G = Aj XC ; H = Jj XA ; bout ; w
        for (int idx = ltid; idx < NS * NS; idx += 128) {
            int r = idx >> 4, cc = idx & 15;
            float a = 0.f, g = 0.f, h = 0.f;
#pragma unroll
            for (int kk = 0; kk < NS; ++kk) {
                a = fmaf(sAj[sub][r][kk], sXAT[sub][cc][kk], a);
                g = fmaf(sAj[sub][r][kk], sXCT[sub][cc][kk], g);
                h = fmaf(sJj[sub][r][kk], sXAT[sub][cc][kk], h);
            }
            oA[sub][dst][r][cc] = a;
            if (storeFull) BA_[k + 1][t][idx] = a;
            sG[sub][r][cc] = g; sH[sub][r][cc] = h;
        }
        if (ltid < NS) {
            float b = sbj[sub][ltid], w = sej[sub][ltid];
#pragma unroll
            for (int kk = 0; kk < NS; ++kk) {
                b = fmaf(sAj[sub][ltid][kk], sXb[sub][kk], b);
                w = fmaf(-sJj[sub][ltid][kk], sXb[sub][kk], w);
            }
            ob[sub][ltid] = b;
            if (storeFull) Bb_[k + 1][t][ltid] = b;
            sw[sub][ltid] = w;
        }
        __syncthreads();

        // Round 2: Cout = G Aj' + Cj ; Jout = Ji + Ai' H ; etaout = etai + Ai' w
        for (int idx = ltid; idx < NS * NS; idx += 128) {
            int r = idx >> 4, cc = idx & 15;
            float cv = sCj[sub][r][cc];
            float jv = oJ[sub][r][cc];
#pragma unroll
            for (int kk = 0; kk < NS; ++kk) {
                cv = fmaf(sG[sub][r][kk], sAj[sub][cc][kk], cv);
                jv = fmaf(oA[sub][src][kk][r], sH[sub][kk][cc], jv);
            }
            oC[sub][r][cc] = cv;
            if (storeFull) BC_[k + 1][t][idx] = cv;
            oJ[sub][r][cc] = jv;
            if (storeFull || k == NLEV - 1) BJ_[k + 1][t][idx] = jv;
        }
        if (ltid < NS) {
            float e = oe[sub][ltid];
#pragma unroll
            for (int kk = 0; kk < NS; ++kk) e = fmaf(oA[sub][src][kk][ltid], sw[sub][kk], e);
            oe[sub][ltid] = e;
            if (storeFull || k == NLEV - 1) Be_[k + 1][t][ltid] = e;
        }
        if (k == NLEV - 2) __syncthreads();      // slot 6 never read cross-CTA
        else publish(&flB[k + 1][bid * FST]);
    }
    // final backward values: slot 7 (BJ_, Be_); oJ/oe hold P_t, eta_t.

    // ---------------- Gains for stage t ----------------
    {
        pollflag(&flB[NLEV][((bid + 1) & 63) * FST]);
        const bool haveP = (t < TT - 1);
        for (int idx = ltid; idx < NS * NS; idx += 128) {
            int r = idx >> 4, cc = idx & 15;
            sAj[sub][r][cc] = haveP ? __ldcg(&BJ_[NLEV][t + 1][idx]) : 0.f;   // P'
        }
        if (ltid < NS) sv[sub][ltid] = haveP ? -__ldcg(&Be_[NLEV][t + 1][ltid]) : 0.f; // p'
        __syncthreads();

        for (int idx = ltid; idx < NS * NS; idx += 128) {
            int i = idx >> 4, j = idx & 15;
            float s = 0.f;
#pragma unroll
            for (int kk = 0; kk < NS; ++kk) s = fmaf(sAj[sub][i][kk], sA[sub][kk][j], s);
            sCj[sub][i][j] = s;                       // P'A
        }
        for (int idx = ltid; idx < NS * NC; idx += 128) {
            int i = idx / NC, j = idx % NC;
            float s = 0.f;
#pragma unroll
            for (int kk = 0; kk < NS; ++kk) s = fmaf(sAj[sub][i][kk], sB[sub][kk][j], s);
            sGb[sub][i][j] = s;                       // P'B
        }
        __syncthreads();

        for (int idx = ltid; idx < NC * NC; idx += 128) {
            int a = idx >> 3, b2 = idx & 7;
            float s = sC[sub][NS + a][NS + b2];
#pragma unroll
            for (int i = 0; i < NS; ++i) s = fmaf(sB[sub][i][a], sGb[sub][i][b2], s);
            sQuu[sub][a][b2] = s;
        }
        for (int idx = ltid; idx < NC * NS; idx += 128) {
            int a = idx >> 4, j = idx & 15;
            float s = sC[sub][NS + a][j];
#pragma unroll
            for (int i = 0; i < NS; ++i) s = fmaf(sB[sub][i][a], sCj[sub][i][j], s);
            sQux[sub][a][j] = s;
        }
        if (ltid < NC) {
            float s = sc[sub][NS + ltid];
#pragma unroll
            for (int i = 0; i < NS; ++i) s = fmaf(sB[sub][i][ltid], sv[sub][i], s);
            squ[sub][ltid] = s;
        }
        __syncthreads();

        if (ltid < 17) {
            float Lm[NC][NC], invd[NC], y[NC];
#pragma unroll
            for (int j = 0; j < NC; ++j)
#pragma unroll
                for (int i = 0; i < NC; ++i)
                    if (i >= j) Lm[i][j] = sQuu[sub][i][j];
#pragma unroll
            for (int j = 0; j < NC; ++j) {
                float r = rsqrtf(Lm[j][j]);
                invd[j] = r;
#pragma unroll
                for (int i = j + 1; i < NC; ++i) Lm[i][j] *= r;
#pragma unroll
                for (int i = j + 1; i < NC; ++i)
#pragma unroll
                    for (int l = j + 1; l <= i; ++l)
                        Lm[i][l] = fmaf(-Lm[i][j], Lm[l][j], Lm[i][l]);
            }
#pragma unroll
            for (int a = 0; a < NC; ++a)
                y[a] = (ltid < NS) ? sQux[sub][a][ltid] : squ[sub][a];
#pragma unroll
            for (int a = 0; a < NC; ++a) {
                float s = y[a];
#pragma unroll
                for (int kk = 0; kk < a; ++kk) s = fmaf(-Lm[a][kk], y[kk], s);
                y[a] = s * invd[a];
            }
#pragma unroll
            for (int a = NC - 1; a >= 0; --a) {
                float s = y[a];
#pragma unroll
                for (int kk = a + 1; kk < NC; ++kk) s = fmaf(-Lm[kk][a], y[kk], s);
                y[a] = s * invd[a];
            }
            if (ltid < NS) {
#pragma unroll
                for (int a = 0; a < NC; ++a) sM[sub][a][ltid] = y[a];  // K
            } else {
#pragma unroll
                for (int a = 0; a < NC; ++a) sm_[sub][a] = y[a];       // kk
            }
        }
        __syncthreads();

        // Acl = A - B K -> forward leaf (sS, FM_[0]); bias -> sv, Fv_[0]
        for (int idx = ltid; idx < NS * NS; idx += 128) {
            int i = idx >> 4, j = idx & 15;
            float s = sA[sub][i][j];
#pragma unroll
            for (int a = 0; a < NC; ++a) s = fmaf(-sB[sub][i][a], sM[sub][a][j], s);
            sS[sub][i][j] = s;
            FM_[0][t][idx] = s;
        }
        if (ltid < NS) {
            float s = 0.f;
#pragma unroll
            for (int a = 0; a < NC; ++a) s = fmaf(-sB[sub][ltid][a], sm_[sub][a], s);
            sv[sub][ltid] = s;
            Fv_[0][t][ltid] = s;
        }
    }
    publish(&flF[0][bid * FST]);

    // ---------------- 7 forward (prefix) levels over (Acl, bias) ----------------
#pragma unroll 1
    for (int k = 0; k < NLEV; ++k) {
        const int d = 1 << k, tl = t - d;
        if (k == NLEV - 1) {
            // d=64: sub1's left partner is sub0's current element; sub0 identity
            if (sub == 1) {
                for (int idx = ltid; idx < NS * NS; idx += 128) {
                    int r = idx >> 4, cc = idx & 15;
                    sXAT[1][r][cc] = sS[0][r][cc];
                }
                if (ltid < NS) sw[1][ltid] = sv[0][ltid];
            } else {
                for (int idx = ltid; idx < NS * NS; idx += 128) {
                    int r = idx >> 4, cc = idx & 15;
                    sXAT[0][r][cc] = (r == cc) ? 1.f : 0.f;
                }
                if (ltid < NS) sw[0][ltid] = 0.f;
            }
        } else {
            pollflag(&flF[k][((bid - d) & 63) * FST]);
            if (tl >= 0) {
                for (int q = ltid; q < NS * NS / 4; q += 128) {
                    int r = q >> 2, c0 = (q & 3) * 4;
                    float4 v = __ldcg((const float4*)&FM_[k][tl][q * 4]);
                    sXAT[sub][r][c0] = v.x; sXAT[sub][r][c0+1] = v.y;
                    sXAT[sub][r][c0+2] = v.z; sXAT[sub][r][c0+3] = v.w;
                }
                if (ltid < NS) sw[sub][ltid] = __ldcg(&Fv_[k][tl][ltid]);
            } else {
                for (int idx = ltid; idx < NS * NS; idx += 128) {
                    int r = idx >> 4, cc = idx & 15;
                    sXAT[sub][r][cc] = (r == cc) ? 1.f : 0.f;
                }
                if (ltid < NS) sw[sub][ltid] = 0.f;
            }
        }
        __syncthreads();

        const int r0 = ltid >> 4, c0 = ltid & 15;
        const int r1 = r0 + 8, c1 = c0;
        float m0 = 0.f, m1 = 0.f, vnew = 0.f;
#pragma unroll
        for (int kk = 0; kk < NS; ++kk) {
            m0 = fmaf(sS[sub][r0][kk], sXAT[sub][kk][c0], m0);
            m1 = fmaf(sS[sub][r1][kk], sXAT[sub][kk][c1], m1);
        }
        if (ltid < NS) {
            vnew = sv[sub][ltid];
#pragma unroll
            for (int kk = 0; kk < NS; ++kk) vnew = fmaf(sS[sub][ltid][kk], sw[sub][kk], vnew);
        }
        __syncthreads();
        sS[sub][r0][c0] = m0;
        sS[sub][r1][c1] = m1;
        if (ltid < NS) sv[sub][ltid] = vnew;
        if (k <= 4 || k == NLEV - 1) {      // slot 6 never read cross-CTA
            FM_[k + 1][t][ltid] = m0;
            FM_[k + 1][t][ltid + 128] = m1;
            if (ltid < NS) Fv_[k + 1][t][ltid] = vnew;
        }
        if (k == NLEV - 2) __syncthreads();
        else publish(&flF[k + 1][bid * FST]);
    }
    // forward prefix final: FM_[7][t], Fv_[7][t]

    // ---------------- Outputs for stage t ----------------
    pollflag(&flF[NLEV][((bid - 1) & 63) * FST]);
    if (ltid < NS) {
        float xi;
        if (t == 0) {
            xi = sx0[ltid];
        } else {
            xi = __ldcg(&Fv_[NLEV][t - 1][ltid]);
#pragma unroll
            for (int q = 0; q < 4; ++q) {
                float4 v = __ldcg((const float4*)&FM_[NLEV][t - 1][ltid * NS + 4 * q]);
                xi = fmaf(v.x, sx0[4 * q + 0], xi); xi = fmaf(v.y, sx0[4 * q + 1], xi);
                xi = fmaf(v.z, sx0[4 * q + 2], xi); xi = fmaf(v.w, sx0[4 * q + 3], xi);
            }
        }
        sx[sub][ltid] = xi;
        out[t * NA + ltid] = xi;
    }
    __syncthreads();
    if (ltid < NC) {
        float s = sm_[sub][ltid];
#pragma unroll
        for (int kk = 0; kk < NS; ++kk) s = fmaf(sM[sub][ltid][kk], sx[sub][kk], s);
        out[t * NA + NS + ltid] = -s;
    } else if (ltid >= 32 && ltid < 48) {
        int i = ltid - 32;
        float s = -oe[sub][i];
#pragma unroll
        for (int kk = 0; kk < NS; ++kk) s = fmaf(oJ[sub][i][kk], sx[sub][kk], s);
        out[TT * NA + t * NS + i] = (t == 0) ? -s : s;
    }

    // ---------------- Last CTA out resets flag state ----------------
    __threadfence();
    __syncthreads();
    if (threadIdx.x == 0)
        slast = (atomicAdd(&bfin, 1u) == (unsigned)NCTA1 - 1) ? 1u : 0u;
    __syncthreads();
    if (slast) {
        for (int q = threadIdx.x; q < (NLEV + 1) * NCTA1; q += 256) {
            flB[q >> 6][(q & 63) * FST] = 0u;
            flF[q >> 6][(q & 63) * FST] = 0u;
        }
        if (threadIdx.x == 0) bfin = 0u;
        __threadfence();
    }
}

extern "C" void kernel_launch(void* const* d_in, const int* in_sizes, int n_in,
                              void* d_out, int out_size) {
    const float* A  = (const float*)d_in[0];
    const float* B  = (const float*)d_in[1];
    const float* x0 = (const float*)d_in[2];
    const float* C  = (const float*)d_in[3];
    const float* c  = (const float*)d_in[4];
    float* out = (float*)d_out;

    lqr_kernel<<<NCTA1, 256>>>(A, B, x0, C, c, out);
}